// round 5
// baseline (speedup 1.0000x reference)
#include <cuda_runtime.h>
#include <cstdint>

#define NN 50000
#define NE 800000
#define NF 128
#define NH 128
#define NC 40

// ---------------- scratch (device globals, no alloc) ----------------
__device__ __align__(16) float g_h[(size_t)NN * 128];    // transformed features
__device__ __align__(16) float g_agg[(size_t)NN * 128];  // aggregation accumulator
__device__ __align__(16) float g_act[(size_t)NN * 128];  // activated output (next layer input)
__device__ float g_dinv[NN];
__device__ int   g_deg[NN];

// ---------------- degree / normalization ----------------
__global__ void k_init_deg() {
    int i = blockIdx.x * blockDim.x + threadIdx.x;
    if (i < NN) g_deg[i] = 1;  // self loop
}

__global__ void k_count(const int* __restrict__ dst) {
    int e = blockIdx.x * blockDim.x + threadIdx.x;
    if (e < NE) atomicAdd(&g_deg[dst[e]], 1);
}

__global__ void k_dinv() {
    int i = blockIdx.x * blockDim.x + threadIdx.x;
    if (i < NN) g_dinv[i] = rsqrtf((float)g_deg[i]);
}

__global__ void k_zero(int n) {
    int i = blockIdx.x * blockDim.x + threadIdx.x;
    if (i < n) g_agg[i] = 0.0f;
}

// ---------------- GEMM: H = X @ W  (X: [n, IN], W: [IN, OUTTOT], col-block OUTB) ----------------
// 16 rows x OUTB cols per block; each thread: 4 rows x 2 cols.
template <int IN, int OUTTOT, int OUTB>
__global__ void k_gemm(const float* __restrict__ Xext, const float* __restrict__ W, int nrows) {
    constexpr int K2 = IN / 2;       // float2 pairs along K
    constexpr int COLT = OUTB / 2;   // column threads (2 cols each)
    constexpr int R = 16;            // rows per block
    __shared__ float2 Wp[K2][OUTB];  // Wp[k2][col] = {W[2k2][col], W[2k2+1][col]}
    __shared__ float2 xs[R][K2];

    const float* X = Xext ? Xext : g_act;
    const int tid = threadIdx.x;
    const int nthr = COLT * 4;
    const int cb = blockIdx.y;
    const int r0 = blockIdx.x * R;

    for (int idx = tid; idx < K2 * OUTB; idx += nthr) {
        int k2 = idx / OUTB, t = idx % OUTB;
        int gc = cb * OUTB + t;
        Wp[k2][t] = make_float2(W[(size_t)(2 * k2) * OUTTOT + gc],
                                W[(size_t)(2 * k2 + 1) * OUTTOT + gc]);
    }
    const float2* X2 = (const float2*)X;
    for (int idx = tid; idx < R * K2; idx += nthr) {
        int r = idx / K2, k2 = idx % K2;
        int row = r0 + r;
        xs[r][k2] = (row < nrows) ? X2[(size_t)row * K2 + k2] : make_float2(0.f, 0.f);
    }
    __syncthreads();

    const int cx = tid % COLT;
    const int ry = tid / COLT;
    const int rb = ry * 4;
    float a00[4], a01[4], a10[4], a11[4];
#pragma unroll
    for (int rr = 0; rr < 4; rr++) { a00[rr] = a01[rr] = a10[rr] = a11[rr] = 0.0f; }

#pragma unroll 8
    for (int k2 = 0; k2 < K2; k2++) {
        float4 w4 = *(const float4*)&Wp[k2][2 * cx];
#pragma unroll
        for (int rr = 0; rr < 4; rr++) {
            float2 xv = xs[rb + rr][k2];
            a00[rr] = fmaf(xv.x, w4.x, a00[rr]);
            a01[rr] = fmaf(xv.y, w4.y, a01[rr]);
            a10[rr] = fmaf(xv.x, w4.z, a10[rr]);
            a11[rr] = fmaf(xv.y, w4.w, a11[rr]);
        }
    }

    const int c0 = cb * OUTB + 2 * cx;
#pragma unroll
    for (int rr = 0; rr < 4; rr++) {
        int row = r0 + rb + rr;
        if (row < nrows) {
            g_h[(size_t)row * OUTTOT + c0]     = a00[rr] + a01[rr];
            g_h[(size_t)row * OUTTOT + c0 + 1] = a10[rr] + a11[rr];
        }
    }
}

// ---------------- edge aggregation: agg[dst] += norm * h[src], one warp per edge ----------------
// Lane handles features lane, lane+32, ... -> every load & every atomic is a fully
// coalesced 128B warp transaction.
template <int OUT>
__global__ void k_edge(const int* __restrict__ src, const int* __restrict__ dst) {
    const int gid = blockIdx.x * blockDim.x + threadIdx.x;
    const int e = gid >> 5;
    const int lane = gid & 31;
    if (e >= NE) return;
    const int s = src[e];
    const int d = dst[e];
    const float nrm = g_dinv[s] * g_dinv[d];
    const float* __restrict__ hp = g_h + (size_t)s * OUT;
    float* ap = g_agg + (size_t)d * OUT;
#pragma unroll
    for (int j = 0; j < (OUT + 31) / 32; j++) {
        int f = j * 32 + lane;
        if (OUT % 32 == 0 || f < OUT) {
            atomicAdd(ap + f, hp[f] * nrm);
        }
    }
}

// ---------------- finalize layers 1/2: act = relu(agg + dinv^2 * h + b) ----------------
template <int OUT>
__global__ void k_finalize(const float* __restrict__ b) {
    int idx = blockIdx.x * blockDim.x + threadIdx.x;
    if (idx >= NN * OUT) return;
    int v = idx / OUT;
    int f = idx % OUT;
    float di = g_dinv[v];
    float val = fmaf(di * di, g_h[idx], g_agg[idx]) + b[f];
    g_act[idx] = fmaxf(val, 0.0f);
}

// ---------------- layer 3 finalize + log_softmax ----------------
__global__ void k_final3(const float* __restrict__ b, float* __restrict__ out) {
    int v = blockIdx.x * blockDim.x + threadIdx.x;
    if (v >= NN) return;
    float di = g_dinv[v];
    float di2 = di * di;
    float z[NC];
    float m = -1e30f;
#pragma unroll
    for (int f = 0; f < NC; f++) {
        float val = fmaf(di2, g_h[(size_t)v * NC + f], g_agg[(size_t)v * NC + f]) + b[f];
        z[f] = val;
        m = fmaxf(m, val);
    }
    float s = 0.0f;
#pragma unroll
    for (int f = 0; f < NC; f++) s += expf(z[f] - m);
    float lse = m + logf(s);
#pragma unroll
    for (int f = 0; f < NC; f++) out[(size_t)v * NC + f] = z[f] - lse;
}

// ---------------- launch ----------------
extern "C" void kernel_launch(void* const* d_in, const int* in_sizes, int n_in,
                              void* d_out, int out_size) {
    const float* x  = (const float*)d_in[0];
    const int* ei   = (const int*)d_in[1];   // int64 in reference -> int32 in harness
    const int* esrc = ei;
    const int* edst = ei + NE;
    const float* W1 = (const float*)d_in[2];
    const float* b1 = (const float*)d_in[3];
    const float* W2 = (const float*)d_in[4];
    const float* b2 = (const float*)d_in[5];
    const float* W3 = (const float*)d_in[6];
    const float* b3 = (const float*)d_in[7];
    float* out = (float*)d_out;

    const int TB = 256;
    const int nodeBlocks = (NN + TB - 1) / TB;
    const int edgeBlocks = (NE + TB - 1) / TB;
    const int edgeWarpBlocks = (NE * 32 + TB - 1) / TB;  // one warp per edge
    const int featBlocks128 = (NN * 128 + TB - 1) / TB;
    const int featBlocks40  = (NN * 40 + TB - 1) / TB;
    const int rowBlocks = (NN + 15) / 16;

    // normalization
    k_init_deg<<<nodeBlocks, TB>>>();
    k_count<<<edgeBlocks, TB>>>(edst);
    k_dinv<<<nodeBlocks, TB>>>();

    // layer 1: h = x@W1 ; agg ; act = relu(...)
    k_gemm<128, 128, 64><<<dim3(rowBlocks, 2), 128>>>(x, W1, NN);
    k_zero<<<featBlocks128, TB>>>(NN * 128);
    k_edge<128><<<edgeWarpBlocks, TB>>>(esrc, edst);
    k_finalize<128><<<featBlocks128, TB>>>(b1);

    // layer 2
    k_gemm<128, 128, 64><<<dim3(rowBlocks, 2), 128>>>(nullptr, W2, NN);
    k_zero<<<featBlocks128, TB>>>(NN * 128);
    k_edge<128><<<edgeWarpBlocks, TB>>>(esrc, edst);
    k_finalize<128><<<featBlocks128, TB>>>(b2);

    // layer 3 + log_softmax
    k_gemm<128, 40, 40><<<dim3(rowBlocks, 1), 80>>>(nullptr, W3, NN);
    k_zero<<<featBlocks40, TB>>>(NN * 40);
    k_edge<40><<<edgeWarpBlocks, TB>>>(esrc, edst);
    k_final3<<<nodeBlocks, TB>>>(b3, out);
}

// round 6
// speedup vs baseline: 1.5954x; 1.5954x over previous
#include <cuda_runtime.h>
#include <cstdint>

#define NN 50000
#define NE 800000
#define NC 40

// ---------------- scratch (device globals, no alloc) ----------------
__device__ __align__(16) float g_h[(size_t)NN * 128];    // dinv-scaled transformed features h'
__device__ __align__(16) float g_act[(size_t)NN * 128];  // activated output (next layer input)
__device__ float g_dinv[NN];
__device__ int   g_cnt[NN];       // in-degree (dst histogram, no self loop)
__device__ int   g_fill[NN];      // scatter cursors
__device__ int   g_rowptr[NN];    // CSR row starts (exclusive scan of cnt)
__device__ int   g_srcs[NE];      // edge sources grouped by dst
__device__ int   g_bsum[64];
__device__ int   g_boff[64];

// ---------------- helpers ----------------
__device__ __forceinline__ float2 ffma2(float2 a, float2 b, float2 c) {
    unsigned long long ua = *reinterpret_cast<unsigned long long*>(&a);
    unsigned long long ub = *reinterpret_cast<unsigned long long*>(&b);
    unsigned long long uc = *reinterpret_cast<unsigned long long*>(&c);
    unsigned long long ud;
    asm("fma.rn.f32x2 %0, %1, %2, %3;" : "=l"(ud) : "l"(ua), "l"(ub), "l"(uc));
    return *reinterpret_cast<float2*>(&ud);
}

// ---------------- degree / CSR build ----------------
__global__ void k_zcnt() {
    int i = blockIdx.x * blockDim.x + threadIdx.x;
    if (i < NN) { g_cnt[i] = 0; g_fill[i] = 0; }
}

__global__ void k_count(const int* __restrict__ dst) {
    int e = blockIdx.x * blockDim.x + threadIdx.x;
    if (e < NE) atomicAdd(&g_cnt[dst[e]], 1);
}

__global__ void k_dinv() {
    int i = blockIdx.x * blockDim.x + threadIdx.x;
    if (i < NN) g_dinv[i] = rsqrtf((float)(g_cnt[i] + 1));  // +1 self loop
}

// block-local exclusive scan of g_cnt (1024/block), block sums to g_bsum
__global__ void k_scan1() {
    int i = blockIdx.x * 1024 + threadIdx.x;
    int v = (i < NN) ? g_cnt[i] : 0;
    int lane = threadIdx.x & 31, wid = threadIdx.x >> 5;
    int x = v;
#pragma unroll
    for (int o = 1; o < 32; o <<= 1) {
        int y = __shfl_up_sync(0xffffffffu, x, o);
        if (lane >= o) x += y;
    }
    __shared__ int ws[32];
    if (lane == 31) ws[wid] = x;
    __syncthreads();
    if (wid == 0) {
        int s = ws[lane];
#pragma unroll
        for (int o = 1; o < 32; o <<= 1) {
            int y = __shfl_up_sync(0xffffffffu, s, o);
            if (lane >= o) s += y;
        }
        ws[lane] = s;
    }
    __syncthreads();
    int incl = x + (wid ? ws[wid - 1] : 0);
    if (i < NN) g_rowptr[i] = incl - v;
    if (threadIdx.x == 1023) g_bsum[blockIdx.x] = incl;
}

__global__ void k_scan2(int nblocks) {
    if (threadIdx.x == 0) {
        int acc = 0;
        for (int b = 0; b < nblocks; b++) { g_boff[b] = acc; acc += g_bsum[b]; }
    }
}

__global__ void k_scan3() {
    int i = blockIdx.x * blockDim.x + threadIdx.x;
    if (i < NN) g_rowptr[i] += g_boff[i >> 10];
}

__global__ void k_scatter(const int* __restrict__ src, const int* __restrict__ dst) {
    int e = blockIdx.x * blockDim.x + threadIdx.x;
    if (e >= NE) return;
    int d = dst[e];
    int pos = g_rowptr[d] + atomicAdd(&g_fill[d], 1);
    g_srcs[pos] = src[e];
}

// ---------------- GEMM v2: g_h[row] = dinv[row] * (X @ W)[row], 128->128 ----------------
// 64x64 tile, 256 threads, 4x4 per thread via outer product, K split into 2x64.
__global__ __launch_bounds__(256) void k_gemm2(const float* __restrict__ Xext,
                                               const float* __restrict__ W) {
    __shared__ float xT[64][68];   // [k_local][row], pad 68: 272B row stride (16B-aligned)
    __shared__ float Wp[64][64];   // [k_local][col]
    const float* X = Xext ? Xext : g_act;
    const int tid = threadIdx.x;
    const int r0 = blockIdx.x * 64;
    const int c0 = blockIdx.y * 64;
    const int tx = tid & 15;       // 16 col groups * 4 cols
    const int ty = tid >> 4;       // 16 row groups * 4 rows

    float2 acc[4][2];              // [col][row pair]
#pragma unroll
    for (int c = 0; c < 4; c++) { acc[c][0] = make_float2(0.f, 0.f); acc[c][1] = make_float2(0.f, 0.f); }

    for (int kt = 0; kt < 2; kt++) {
        // load x tile transposed: 64 rows x 16 float4 (k-quads)
        for (int idx = tid; idx < 64 * 16; idx += 256) {
            int row = idx >> 4, kq = idx & 15;
            int grow = r0 + row;
            float4 v = (grow < NN) ? ((const float4*)X)[(size_t)grow * 32 + kt * 16 + kq]
                                   : make_float4(0.f, 0.f, 0.f, 0.f);
            xT[4 * kq + 0][row] = v.x;
            xT[4 * kq + 1][row] = v.y;
            xT[4 * kq + 2][row] = v.z;
            xT[4 * kq + 3][row] = v.w;
        }
        // load W tile: 64 k x 16 float4
        for (int idx = tid; idx < 64 * 16; idx += 256) {
            int k = idx >> 4, cq = idx & 15;
            ((float4*)&Wp[k][0])[cq] = ((const float4*)W)[(size_t)(kt * 64 + k) * 32 + (c0 >> 2) + cq];
        }
        __syncthreads();

#pragma unroll 16
        for (int k = 0; k < 64; k++) {
            float4 xv = *(const float4*)&xT[k][4 * ty];
            float4 wv = *(const float4*)&Wp[k][4 * tx];
            float2 xa = make_float2(xv.x, xv.y);
            float2 xb = make_float2(xv.z, xv.w);
            acc[0][0] = ffma2(xa, make_float2(wv.x, wv.x), acc[0][0]);
            acc[0][1] = ffma2(xb, make_float2(wv.x, wv.x), acc[0][1]);
            acc[1][0] = ffma2(xa, make_float2(wv.y, wv.y), acc[1][0]);
            acc[1][1] = ffma2(xb, make_float2(wv.y, wv.y), acc[1][1]);
            acc[2][0] = ffma2(xa, make_float2(wv.z, wv.z), acc[2][0]);
            acc[2][1] = ffma2(xb, make_float2(wv.z, wv.z), acc[2][1]);
            acc[3][0] = ffma2(xa, make_float2(wv.w, wv.w), acc[3][0]);
            acc[3][1] = ffma2(xb, make_float2(wv.w, wv.w), acc[3][1]);
        }
        __syncthreads();
    }

    // epilogue: scale by dinv[row], float4 store per row
#pragma unroll
    for (int p = 0; p < 4; p++) {
        int row = r0 + 4 * ty + p;
        if (row < NN) {
            float di = g_dinv[row];
            float a0 = (p & 1) ? acc[0][p >> 1].y : acc[0][p >> 1].x;
            float a1 = (p & 1) ? acc[1][p >> 1].y : acc[1][p >> 1].x;
            float a2 = (p & 1) ? acc[2][p >> 1].y : acc[2][p >> 1].x;
            float a3 = (p & 1) ? acc[3][p >> 1].y : acc[3][p >> 1].x;
            *(float4*)&g_h[(size_t)row * 128 + c0 + 4 * tx] =
                make_float4(di * a0, di * a1, di * a2, di * a3);
        }
    }
}

// ---------------- GEMM 128->40 (layer 3), dinv-scaled epilogue ----------------
__global__ void k_gemm3(const float* __restrict__ W) {
    constexpr int K2 = 64, OUTTOT = 40, OUTB = 40, COLT = 20, R = 16;
    __shared__ float2 Wp[K2][OUTB];
    __shared__ float2 xs[R][K2];
    const float* X = g_act;
    const int tid = threadIdx.x;
    const int nthr = COLT * 4;  // 80
    const int r0 = blockIdx.x * R;

    for (int idx = tid; idx < K2 * OUTB; idx += nthr) {
        int k2 = idx / OUTB, t = idx % OUTB;
        Wp[k2][t] = make_float2(W[(size_t)(2 * k2) * OUTTOT + t],
                                W[(size_t)(2 * k2 + 1) * OUTTOT + t]);
    }
    const float2* X2 = (const float2*)X;
    for (int idx = tid; idx < R * K2; idx += nthr) {
        int r = idx / K2, k2 = idx % K2;
        int row = r0 + r;
        xs[r][k2] = (row < NN) ? X2[(size_t)row * K2 + k2] : make_float2(0.f, 0.f);
    }
    __syncthreads();

    const int cx = tid % COLT;
    const int ry = tid / COLT;
    const int rb = ry * 4;
    float a00[4], a01[4], a10[4], a11[4];
#pragma unroll
    for (int rr = 0; rr < 4; rr++) { a00[rr] = a01[rr] = a10[rr] = a11[rr] = 0.0f; }

#pragma unroll 8
    for (int k2 = 0; k2 < K2; k2++) {
        float4 w4 = *(const float4*)&Wp[k2][2 * cx];
#pragma unroll
        for (int rr = 0; rr < 4; rr++) {
            float2 xv = xs[rb + rr][k2];
            a00[rr] = fmaf(xv.x, w4.x, a00[rr]);
            a01[rr] = fmaf(xv.y, w4.y, a01[rr]);
            a10[rr] = fmaf(xv.x, w4.z, a10[rr]);
            a11[rr] = fmaf(xv.y, w4.w, a11[rr]);
        }
    }

    const int c0 = 2 * cx;
#pragma unroll
    for (int rr = 0; rr < 4; rr++) {
        int row = r0 + rb + rr;
        if (row < NN) {
            float di = g_dinv[row];
            g_h[(size_t)row * OUTTOT + c0]     = di * (a00[rr] + a01[rr]);
            g_h[(size_t)row * OUTTOT + c0 + 1] = di * (a10[rr] + a11[rr]);
        }
    }
}

// ---------------- fused aggregation (warp per node), 128-wide + bias + relu ----------------
__global__ void k_agg128(const float* __restrict__ bias) {
    const int gid = blockIdx.x * blockDim.x + threadIdx.x;
    const int v = gid >> 5;
    if (v >= NN) return;
    const int lane = gid & 31;
    const float4* __restrict__ H = (const float4*)g_h;
    float4 acc = H[v * 32 + lane];  // self loop h'[v]
    const int n = g_cnt[v];
    const int* __restrict__ sp = g_srcs + g_rowptr[v];
    int j = 0;
    for (; j + 4 <= n; j += 4) {
        int s1 = sp[j], s2 = sp[j + 1], s3 = sp[j + 2], s4 = sp[j + 3];
        float4 t1 = H[s1 * 32 + lane];
        float4 t2 = H[s2 * 32 + lane];
        float4 t3 = H[s3 * 32 + lane];
        float4 t4 = H[s4 * 32 + lane];
        acc.x += (t1.x + t2.x) + (t3.x + t4.x);
        acc.y += (t1.y + t2.y) + (t3.y + t4.y);
        acc.z += (t1.z + t2.z) + (t3.z + t4.z);
        acc.w += (t1.w + t2.w) + (t3.w + t4.w);
    }
    for (; j < n; j++) {
        float4 t = H[sp[j] * 32 + lane];
        acc.x += t.x; acc.y += t.y; acc.z += t.z; acc.w += t.w;
    }
    const float di = g_dinv[v];
    const float4 bb = ((const float4*)bias)[lane];
    float4 o;
    o.x = fmaxf(fmaf(di, acc.x, bb.x), 0.f);
    o.y = fmaxf(fmaf(di, acc.y, bb.y), 0.f);
    o.z = fmaxf(fmaf(di, acc.z, bb.z), 0.f);
    o.w = fmaxf(fmaf(di, acc.w, bb.w), 0.f);
    ((float4*)g_act)[v * 32 + lane] = o;
}

// ---------------- fused layer-3 aggregation + bias + log_softmax ----------------
__global__ void k_agg40(const float* __restrict__ bias, float* __restrict__ out) {
    const int gid = blockIdx.x * blockDim.x + threadIdx.x;
    const int v = gid >> 5;
    if (v >= NN) return;
    const int lane = gid & 31;
    const bool act = lane < 10;  // 40 feats = 10 float4
    const float4* __restrict__ H = (const float4*)g_h;
    float4 acc = act ? H[v * 10 + lane] : make_float4(0.f, 0.f, 0.f, 0.f);
    const int n = g_cnt[v];
    const int* __restrict__ sp = g_srcs + g_rowptr[v];
    int j = 0;
    for (; j + 2 <= n; j += 2) {
        int s1 = sp[j], s2 = sp[j + 1];
        if (act) {
            float4 t1 = H[s1 * 10 + lane];
            float4 t2 = H[s2 * 10 + lane];
            acc.x += t1.x + t2.x; acc.y += t1.y + t2.y;
            acc.z += t1.z + t2.z; acc.w += t1.w + t2.w;
        }
    }
    if (j < n && act) {
        float4 t = H[sp[j] * 10 + lane];
        acc.x += t.x; acc.y += t.y; acc.z += t.z; acc.w += t.w;
    }
    const float di = g_dinv[v];
    float4 z = make_float4(0.f, 0.f, 0.f, 0.f);
    if (act) {
        const float4 bb = ((const float4*)bias)[lane];
        z.x = fmaf(di, acc.x, bb.x);
        z.y = fmaf(di, acc.y, bb.y);
        z.z = fmaf(di, acc.z, bb.z);
        z.w = fmaf(di, acc.w, bb.w);
    }
    float m = act ? fmaxf(fmaxf(z.x, z.y), fmaxf(z.z, z.w)) : -1e30f;
#pragma unroll
    for (int o = 16; o >= 1; o >>= 1) m = fmaxf(m, __shfl_xor_sync(0xffffffffu, m, o));
    float s = act ? (expf(z.x - m) + expf(z.y - m) + expf(z.z - m) + expf(z.w - m)) : 0.f;
#pragma unroll
    for (int o = 16; o >= 1; o >>= 1) s += __shfl_xor_sync(0xffffffffu, s, o);
    const float lse = m + logf(s);
    if (act) {
        ((float4*)out)[v * 10 + lane] =
            make_float4(z.x - lse, z.y - lse, z.z - lse, z.w - lse);
    }
}

// ---------------- launch ----------------
extern "C" void kernel_launch(void* const* d_in, const int* in_sizes, int n_in,
                              void* d_out, int out_size) {
    const float* x  = (const float*)d_in[0];
    const int* ei   = (const int*)d_in[1];
    const int* esrc = ei;
    const int* edst = ei + NE;
    const float* W1 = (const float*)d_in[2];
    const float* b1 = (const float*)d_in[3];
    const float* W2 = (const float*)d_in[4];
    const float* b2 = (const float*)d_in[5];
    const float* W3 = (const float*)d_in[6];
    const float* b3 = (const float*)d_in[7];
    float* out = (float*)d_out;

    const int TB = 256;
    const int nodeBlocks = (NN + TB - 1) / TB;
    const int edgeBlocks = (NE + TB - 1) / TB;
    const int warpBlocks = (NN * 32 + TB - 1) / TB;   // warp per node
    const int scanBlocks = (NN + 1023) / 1024;        // 49
    const int gemmRows = (NN + 63) / 64;              // 782
    const int gemm3Rows = (NN + 15) / 16;             // 3125

    // degree + CSR build
    k_zcnt<<<nodeBlocks, TB>>>();
    k_count<<<edgeBlocks, TB>>>(edst);
    k_dinv<<<nodeBlocks, TB>>>();
    k_scan1<<<scanBlocks, 1024>>>();
    k_scan2<<<1, 32>>>(scanBlocks);
    k_scan3<<<nodeBlocks, TB>>>();
    k_scatter<<<edgeBlocks, TB>>>(esrc, edst);

    // layer 1
    k_gemm2<<<dim3(gemmRows, 2), 256>>>(x, W1);
    k_agg128<<<warpBlocks, TB>>>(b1);
    // layer 2
    k_gemm2<<<dim3(gemmRows, 2), 256>>>(nullptr, W2);
    k_agg128<<<warpBlocks, TB>>>(b2);
    // layer 3
    k_gemm3<<<gemm3Rows, 80>>>(W3);
    k_agg40<<<warpBlocks, TB>>>(b3, out);
}

// round 7
// speedup vs baseline: 2.0817x; 1.3048x over previous
#include <cuda_runtime.h>
#include <cstdint>

#define NN 50000
#define NE 800000
#define NC 40

// ---------------- scratch (device globals, no alloc) ----------------
__device__ __align__(16) float g_h[(size_t)NN * 128];    // dinv-scaled transformed features h'
__device__ __align__(16) float g_act[(size_t)NN * 128];  // activated output (next layer input)
__device__ float g_dinv[NN];
__device__ int   g_cnt[NN];       // in-degree (dst histogram, no self loop)
__device__ int   g_fill[NN];      // scatter cursors
__device__ int   g_rowptr[NN];    // CSR row starts (exclusive scan of cnt)
__device__ int   g_srcs[NE];      // edge sources grouped by dst
__device__ int   g_bsum[64];
__device__ int   g_boff[64];

// ---------------- helpers ----------------
__device__ __forceinline__ float2 ffma2(float2 a, float2 b, float2 c) {
    unsigned long long ua = *reinterpret_cast<unsigned long long*>(&a);
    unsigned long long ub = *reinterpret_cast<unsigned long long*>(&b);
    unsigned long long uc = *reinterpret_cast<unsigned long long*>(&c);
    unsigned long long ud;
    asm("fma.rn.f32x2 %0, %1, %2, %3;" : "=l"(ud) : "l"(ua), "l"(ub), "l"(uc));
    return *reinterpret_cast<float2*>(&ud);
}

// ---------------- degree / CSR build ----------------
__global__ void k_zcnt() {
    int i = blockIdx.x * blockDim.x + threadIdx.x;
    if (i < NN) { g_cnt[i] = 0; g_fill[i] = 0; }
}

__global__ void k_count(const int* __restrict__ dst) {
    int e = blockIdx.x * blockDim.x + threadIdx.x;
    if (e < NE) atomicAdd(&g_cnt[dst[e]], 1);
}

// fused: dinv[i] = rsqrt(cnt+1)  AND  block-local exclusive scan of cnt
__global__ void k_scan1() {
    int i = blockIdx.x * 1024 + threadIdx.x;
    int v = (i < NN) ? g_cnt[i] : 0;
    if (i < NN) g_dinv[i] = rsqrtf((float)(v + 1));  // +1 self loop
    int lane = threadIdx.x & 31, wid = threadIdx.x >> 5;
    int x = v;
#pragma unroll
    for (int o = 1; o < 32; o <<= 1) {
        int y = __shfl_up_sync(0xffffffffu, x, o);
        if (lane >= o) x += y;
    }
    __shared__ int ws[32];
    if (lane == 31) ws[wid] = x;
    __syncthreads();
    if (wid == 0) {
        int s = ws[lane];
#pragma unroll
        for (int o = 1; o < 32; o <<= 1) {
            int y = __shfl_up_sync(0xffffffffu, s, o);
            if (lane >= o) s += y;
        }
        ws[lane] = s;
    }
    __syncthreads();
    int incl = x + (wid ? ws[wid - 1] : 0);
    if (i < NN) g_rowptr[i] = incl - v;
    if (threadIdx.x == 1023) g_bsum[blockIdx.x] = incl;
}

// one-warp scan over <=64 block sums
__global__ void k_scan2(int nb) {
    int lane = threadIdx.x;
    int a = (lane < nb) ? g_bsum[lane] : 0;
    int b = (lane + 32 < nb) ? g_bsum[lane + 32] : 0;
    int va = a, vb = b;
#pragma unroll
    for (int o = 1; o < 32; o <<= 1) {
        int y = __shfl_up_sync(0xffffffffu, a, o);
        if (lane >= o) a += y;
    }
    int tot = __shfl_sync(0xffffffffu, a, 31);
#pragma unroll
    for (int o = 1; o < 32; o <<= 1) {
        int y = __shfl_up_sync(0xffffffffu, b, o);
        if (lane >= o) b += y;
    }
    b += tot;
    if (lane < nb) g_boff[lane] = a - va;
    if (lane + 32 < nb) g_boff[lane + 32] = b - vb;
}

__global__ void k_scan3() {
    int i = blockIdx.x * blockDim.x + threadIdx.x;
    if (i < NN) g_rowptr[i] += g_boff[i >> 10];
}

__global__ void k_scatter(const int* __restrict__ src, const int* __restrict__ dst) {
    int e = blockIdx.x * blockDim.x + threadIdx.x;
    if (e >= NE) return;
    int d = dst[e];
    int pos = g_rowptr[d] + atomicAdd(&g_fill[d], 1);
    g_srcs[pos] = src[e];
}

// ---------------- GEMM v3: g_h[row] = dinv[row] * (X @ W)[row], 128->128 ----------------
// 64 rows x 64 cols per block, full K=128 strip in smem, single __syncthreads.
// 256 threads, each computes 4x4 via outer product (FFMA2).
__global__ __launch_bounds__(256) void k_gemm2(const float* __restrict__ Xext,
                                               const float* __restrict__ W) {
    extern __shared__ float smem[];
    float (*xT)[68] = (float (*)[68])smem;               // [128][68] transposed x
    float (*Wp)[64] = (float (*)[64])(smem + 128 * 68);  // [128][64]
    const float* X = Xext ? Xext : g_act;
    const int tid = threadIdx.x;
    const int r0 = blockIdx.x * 64;
    const int c0 = blockIdx.y * 64;
    const int tx = tid & 15;
    const int ty = tid >> 4;

    // load x tile transposed: 64 rows x 32 float4 (full K)
    for (int idx = tid; idx < 64 * 32; idx += 256) {
        int row = idx >> 5, kq = idx & 31;
        int grow = r0 + row;
        float4 v = (grow < NN) ? ((const float4*)X)[(size_t)grow * 32 + kq]
                               : make_float4(0.f, 0.f, 0.f, 0.f);
        xT[4 * kq + 0][row] = v.x;
        xT[4 * kq + 1][row] = v.y;
        xT[4 * kq + 2][row] = v.z;
        xT[4 * kq + 3][row] = v.w;
    }
    // load W strip: 128 k x 16 float4
    for (int idx = tid; idx < 128 * 16; idx += 256) {
        int k = idx >> 4, cq = idx & 15;
        ((float4*)&Wp[k][0])[cq] = ((const float4*)W)[(size_t)k * 32 + (c0 >> 2) + cq];
    }
    __syncthreads();

    float2 acc[4][2];
#pragma unroll
    for (int c = 0; c < 4; c++) { acc[c][0] = make_float2(0.f, 0.f); acc[c][1] = make_float2(0.f, 0.f); }

#pragma unroll 16
    for (int k = 0; k < 128; k++) {
        float4 xv = *(const float4*)&xT[k][4 * ty];
        float4 wv = *(const float4*)&Wp[k][4 * tx];
        float2 xa = make_float2(xv.x, xv.y);
        float2 xb = make_float2(xv.z, xv.w);
        acc[0][0] = ffma2(xa, make_float2(wv.x, wv.x), acc[0][0]);
        acc[0][1] = ffma2(xb, make_float2(wv.x, wv.x), acc[0][1]);
        acc[1][0] = ffma2(xa, make_float2(wv.y, wv.y), acc[1][0]);
        acc[1][1] = ffma2(xb, make_float2(wv.y, wv.y), acc[1][1]);
        acc[2][0] = ffma2(xa, make_float2(wv.z, wv.z), acc[2][0]);
        acc[2][1] = ffma2(xb, make_float2(wv.z, wv.z), acc[2][1]);
        acc[3][0] = ffma2(xa, make_float2(wv.w, wv.w), acc[3][0]);
        acc[3][1] = ffma2(xb, make_float2(wv.w, wv.w), acc[3][1]);
    }

#pragma unroll
    for (int p = 0; p < 4; p++) {
        int row = r0 + 4 * ty + p;
        if (row < NN) {
            float di = g_dinv[row];
            float a0 = (p & 1) ? acc[0][p >> 1].y : acc[0][p >> 1].x;
            float a1 = (p & 1) ? acc[1][p >> 1].y : acc[1][p >> 1].x;
            float a2 = (p & 1) ? acc[2][p >> 1].y : acc[2][p >> 1].x;
            float a3 = (p & 1) ? acc[3][p >> 1].y : acc[3][p >> 1].x;
            *(float4*)&g_h[(size_t)row * 128 + c0 + 4 * tx] =
                make_float4(di * a0, di * a1, di * a2, di * a3);
        }
    }
}

// ---------------- GEMM 128->40 (layer 3), dinv-scaled epilogue ----------------
__global__ void k_gemm3(const float* __restrict__ W) {
    constexpr int K2 = 64, OUTTOT = 40, OUTB = 40, COLT = 20, R = 16;
    __shared__ float2 Wp[K2][OUTB];
    __shared__ float2 xs[R][K2];
    const float* X = g_act;
    const int tid = threadIdx.x;
    const int nthr = COLT * 4;  // 80
    const int r0 = blockIdx.x * R;

    for (int idx = tid; idx < K2 * OUTB; idx += nthr) {
        int k2 = idx / OUTB, t = idx % OUTB;
        Wp[k2][t] = make_float2(W[(size_t)(2 * k2) * OUTTOT + t],
                                W[(size_t)(2 * k2 + 1) * OUTTOT + t]);
    }
    const float2* X2 = (const float2*)X;
    for (int idx = tid; idx < R * K2; idx += nthr) {
        int r = idx / K2, k2 = idx % K2;
        int row = r0 + r;
        xs[r][k2] = (row < NN) ? X2[(size_t)row * K2 + k2] : make_float2(0.f, 0.f);
    }
    __syncthreads();

    const int cx = tid % COLT;
    const int ry = tid / COLT;
    const int rb = ry * 4;
    float a00[4], a01[4], a10[4], a11[4];
#pragma unroll
    for (int rr = 0; rr < 4; rr++) { a00[rr] = a01[rr] = a10[rr] = a11[rr] = 0.0f; }

#pragma unroll 8
    for (int k2 = 0; k2 < K2; k2++) {
        float4 w4 = *(const float4*)&Wp[k2][2 * cx];
#pragma unroll
        for (int rr = 0; rr < 4; rr++) {
            float2 xv = xs[rb + rr][k2];
            a00[rr] = fmaf(xv.x, w4.x, a00[rr]);
            a01[rr] = fmaf(xv.y, w4.y, a01[rr]);
            a10[rr] = fmaf(xv.x, w4.z, a10[rr]);
            a11[rr] = fmaf(xv.y, w4.w, a11[rr]);
        }
    }

    const int c0 = 2 * cx;
#pragma unroll
    for (int rr = 0; rr < 4; rr++) {
        int row = r0 + rb + rr;
        if (row < NN) {
            float di = g_dinv[row];
            g_h[(size_t)row * OUTTOT + c0]     = di * (a00[rr] + a01[rr]);
            g_h[(size_t)row * OUTTOT + c0 + 1] = di * (a10[rr] + a11[rr]);
        }
    }
}

// ---------------- fused aggregation (warp per node), 128-wide + bias + relu ----------------
__global__ void k_agg128(const float* __restrict__ bias) {
    const int gid = blockIdx.x * blockDim.x + threadIdx.x;
    const int v = gid >> 5;
    if (v >= NN) return;
    const int lane = gid & 31;
    const float4* __restrict__ H = (const float4*)g_h;
    float4 acc = H[v * 32 + lane];  // self loop h'[v]
    const int n = g_cnt[v];
    const int* __restrict__ sp = g_srcs + g_rowptr[v];
    int j = 0;
    for (; j + 4 <= n; j += 4) {
        int s1 = sp[j], s2 = sp[j + 1], s3 = sp[j + 2], s4 = sp[j + 3];
        float4 t1 = H[s1 * 32 + lane];
        float4 t2 = H[s2 * 32 + lane];
        float4 t3 = H[s3 * 32 + lane];
        float4 t4 = H[s4 * 32 + lane];
        acc.x += (t1.x + t2.x) + (t3.x + t4.x);
        acc.y += (t1.y + t2.y) + (t3.y + t4.y);
        acc.z += (t1.z + t2.z) + (t3.z + t4.z);
        acc.w += (t1.w + t2.w) + (t3.w + t4.w);
    }
    for (; j < n; j++) {
        float4 t = H[sp[j] * 32 + lane];
        acc.x += t.x; acc.y += t.y; acc.z += t.z; acc.w += t.w;
    }
    const float di = g_dinv[v];
    const float4 bb = ((const float4*)bias)[lane];
    float4 o;
    o.x = fmaxf(fmaf(di, acc.x, bb.x), 0.f);
    o.y = fmaxf(fmaf(di, acc.y, bb.y), 0.f);
    o.z = fmaxf(fmaf(di, acc.z, bb.z), 0.f);
    o.w = fmaxf(fmaf(di, acc.w, bb.w), 0.f);
    ((float4*)g_act)[v * 32 + lane] = o;
}

// ---------------- fused layer-3 aggregation + bias + log_softmax ----------------
__global__ void k_agg40(const float* __restrict__ bias, float* __restrict__ out) {
    const int gid = blockIdx.x * blockDim.x + threadIdx.x;
    const int v = gid >> 5;
    if (v >= NN) return;
    const int lane = gid & 31;
    const bool act = lane < 10;  // 40 feats = 10 float4
    const float4* __restrict__ H = (const float4*)g_h;
    float4 acc = act ? H[v * 10 + lane] : make_float4(0.f, 0.f, 0.f, 0.f);
    const int n = g_cnt[v];
    const int* __restrict__ sp = g_srcs + g_rowptr[v];
    int j = 0;
    for (; j + 2 <= n; j += 2) {
        int s1 = sp[j], s2 = sp[j + 1];
        if (act) {
            float4 t1 = H[s1 * 10 + lane];
            float4 t2 = H[s2 * 10 + lane];
            acc.x += t1.x + t2.x; acc.y += t1.y + t2.y;
            acc.z += t1.z + t2.z; acc.w += t1.w + t2.w;
        }
    }
    if (j < n && act) {
        float4 t = H[sp[j] * 10 + lane];
        acc.x += t.x; acc.y += t.y; acc.z += t.z; acc.w += t.w;
    }
    const float di = g_dinv[v];
    float4 z = make_float4(0.f, 0.f, 0.f, 0.f);
    if (act) {
        const float4 bb = ((const float4*)bias)[lane];
        z.x = fmaf(di, acc.x, bb.x);
        z.y = fmaf(di, acc.y, bb.y);
        z.z = fmaf(di, acc.z, bb.z);
        z.w = fmaf(di, acc.w, bb.w);
    }
    float m = act ? fmaxf(fmaxf(z.x, z.y), fmaxf(z.z, z.w)) : -1e30f;
#pragma unroll
    for (int o = 16; o >= 1; o >>= 1) m = fmaxf(m, __shfl_xor_sync(0xffffffffu, m, o));
    float s = act ? (expf(z.x - m) + expf(z.y - m) + expf(z.z - m) + expf(z.w - m)) : 0.f;
#pragma unroll
    for (int o = 16; o >= 1; o >>= 1) s += __shfl_xor_sync(0xffffffffu, s, o);
    const float lse = m + logf(s);
    if (act) {
        ((float4*)out)[v * 10 + lane] =
            make_float4(z.x - lse, z.y - lse, z.z - lse, z.w - lse);
    }
}

// ---------------- launch ----------------
extern "C" void kernel_launch(void* const* d_in, const int* in_sizes, int n_in,
                              void* d_out, int out_size) {
    const float* x  = (const float*)d_in[0];
    const int* ei   = (const int*)d_in[1];
    const int* esrc = ei;
    const int* edst = ei + NE;
    const float* W1 = (const float*)d_in[2];
    const float* b1 = (const float*)d_in[3];
    const float* W2 = (const float*)d_in[4];
    const float* b2 = (const float*)d_in[5];
    const float* W3 = (const float*)d_in[6];
    const float* b3 = (const float*)d_in[7];
    float* out = (float*)d_out;

    const int TB = 256;
    const int nodeBlocks = (NN + TB - 1) / TB;
    const int edgeBlocks = (NE + TB - 1) / TB;
    const int warpBlocks = (NN * 32 + TB - 1) / TB;   // warp per node
    const int scanBlocks = (NN + 1023) / 1024;        // 49
    const int gemmRows = (NN + 63) / 64;              // 782
    const int gemm3Rows = (NN + 15) / 16;             // 3125
    const int gemmSmem = (128 * 68 + 128 * 64) * 4;   // 67584 B

    static bool attrDone = false;  // host-side config, same every call (no device work)
    if (!attrDone) {
        cudaFuncSetAttribute(k_gemm2, cudaFuncAttributeMaxDynamicSharedMemorySize, gemmSmem);
        attrDone = true;
    }

    // CSR build (launch index 3 = k_gemm2 for ncu)
    k_zcnt<<<nodeBlocks, TB>>>();                       // 0
    k_count<<<edgeBlocks, TB>>>(edst);                  // 1
    k_scan1<<<scanBlocks, 1024>>>();                    // 2 (also computes dinv)
    k_gemm2<<<dim3(gemmRows, 2), 256, gemmSmem>>>(x, W1); // 3  <- profiled
    k_scan2<<<1, 32>>>(scanBlocks);                     // 4
    k_scan3<<<nodeBlocks, TB>>>();                      // 5
    k_scatter<<<edgeBlocks, TB>>>(esrc, edst);          // 6

    // layer 1 aggregation
    k_agg128<<<warpBlocks, TB>>>(b1);                   // 7
    // layer 2
    k_gemm2<<<dim3(gemmRows, 2), 256, gemmSmem>>>(nullptr, W2); // 8
    k_agg128<<<warpBlocks, TB>>>(b2);                   // 9
    // layer 3
    k_gemm3<<<gemm3Rows, 80>>>(W3);                     // 10
    k_agg40<<<warpBlocks, TB>>>(b3, out);               // 11
}

// round 8
// speedup vs baseline: 2.4996x; 1.2007x over previous
#include <cuda_runtime.h>
#include <cstdint>

#define NN 50000
#define NE 800000
#define NC 40

// ---------------- scratch (device globals, no alloc) ----------------
__device__ __align__(16) float g_h[(size_t)NN * 128];    // dinv-scaled transformed features h'
__device__ __align__(16) float g_act[(size_t)NN * 128];  // activated output (next layer input)
__device__ float g_dinv[NN];
__device__ int   g_cnt[NN];       // in-degree (dst histogram, no self loop)
__device__ int   g_fill[NN];      // scatter cursors
__device__ int   g_rowptr[NN];    // CSR row starts (exclusive scan of cnt)
__device__ int   g_srcs[NE];      // edge sources grouped by dst
__device__ int   g_bsum[64];
__device__ int   g_boff[64];

// ---------------- helpers ----------------
__device__ __forceinline__ float2 ffma2(float2 a, float2 b, float2 c) {
    unsigned long long ua = *reinterpret_cast<unsigned long long*>(&a);
    unsigned long long ub = *reinterpret_cast<unsigned long long*>(&b);
    unsigned long long uc = *reinterpret_cast<unsigned long long*>(&c);
    unsigned long long ud;
    asm("fma.rn.f32x2 %0, %1, %2, %3;" : "=l"(ud) : "l"(ua), "l"(ub), "l"(uc));
    return *reinterpret_cast<float2*>(&ud);
}

// ---------------- degree / CSR build ----------------
__global__ void k_zcnt() {
    int i = blockIdx.x * blockDim.x + threadIdx.x;
    if (i < NN) { g_cnt[i] = 0; g_fill[i] = 0; }
}

__global__ void k_count(const int* __restrict__ dst) {
    int e = blockIdx.x * blockDim.x + threadIdx.x;
    if (e < NE) atomicAdd(&g_cnt[dst[e]], 1);
}

// fused: dinv[i] = rsqrt(cnt+1)  AND  block-local exclusive scan of cnt
__global__ void k_scan1() {
    int i = blockIdx.x * 1024 + threadIdx.x;
    int v = (i < NN) ? g_cnt[i] : 0;
    if (i < NN) g_dinv[i] = rsqrtf((float)(v + 1));  // +1 self loop
    int lane = threadIdx.x & 31, wid = threadIdx.x >> 5;
    int x = v;
#pragma unroll
    for (int o = 1; o < 32; o <<= 1) {
        int y = __shfl_up_sync(0xffffffffu, x, o);
        if (lane >= o) x += y;
    }
    __shared__ int ws[32];
    if (lane == 31) ws[wid] = x;
    __syncthreads();
    if (wid == 0) {
        int s = ws[lane];
#pragma unroll
        for (int o = 1; o < 32; o <<= 1) {
            int y = __shfl_up_sync(0xffffffffu, s, o);
            if (lane >= o) s += y;
        }
        ws[lane] = s;
    }
    __syncthreads();
    int incl = x + (wid ? ws[wid - 1] : 0);
    if (i < NN) g_rowptr[i] = incl - v;
    if (threadIdx.x == 1023) g_bsum[blockIdx.x] = incl;
}

// one-warp scan over <=64 block sums
__global__ void k_scan2(int nb) {
    int lane = threadIdx.x;
    int a = (lane < nb) ? g_bsum[lane] : 0;
    int b = (lane + 32 < nb) ? g_bsum[lane + 32] : 0;
    int va = a, vb = b;
#pragma unroll
    for (int o = 1; o < 32; o <<= 1) {
        int y = __shfl_up_sync(0xffffffffu, a, o);
        if (lane >= o) a += y;
    }
    int tot = __shfl_sync(0xffffffffu, a, 31);
#pragma unroll
    for (int o = 1; o < 32; o <<= 1) {
        int y = __shfl_up_sync(0xffffffffu, b, o);
        if (lane >= o) b += y;
    }
    b += tot;
    if (lane < nb) g_boff[lane] = a - va;
    if (lane + 32 < nb) g_boff[lane + 32] = b - vb;
}

__global__ void k_scan3() {
    int i = blockIdx.x * blockDim.x + threadIdx.x;
    if (i < NN) g_rowptr[i] += g_boff[i >> 10];
}

__global__ void k_scatter(const int* __restrict__ src, const int* __restrict__ dst) {
    int e = blockIdx.x * blockDim.x + threadIdx.x;
    if (e >= NE) return;
    int d = dst[e];
    int pos = g_rowptr[d] + atomicAdd(&g_fill[d], 1);
    g_srcs[pos] = src[e];
}

// ---------------- GEMM v4: g_h[row] = dinv[row] * (X @ W)[row], 128->128 ----------------
// 128x128 output tile per block, 256 threads, 8x8 per thread (1B smem per FMA).
// K split into 4 tiles of 32. Both smem and fma pipes ~balanced.
__global__ __launch_bounds__(256, 2) void k_gemm2(const float* __restrict__ Xext,
                                                  const float* __restrict__ W) {
    __shared__ float xT[32][132];  // [k_local][row] transposed x, pad 132 (528B, 16B-aligned)
    __shared__ float Wp[32][128];  // [k_local][col]
    const float* X = Xext ? Xext : g_act;
    const int tid = threadIdx.x;
    const int r0 = blockIdx.x * 128;
    const int tx = tid & 15;       // 16 col groups * 8 cols
    const int ty = tid >> 4;       // 16 row groups * 8 rows

    float2 acc[8][4];              // [col][row-pair]
#pragma unroll
    for (int c = 0; c < 8; c++)
#pragma unroll
        for (int rp = 0; rp < 4; rp++) acc[c][rp] = make_float2(0.f, 0.f);

    for (int kt = 0; kt < 4; kt++) {
        // load x tile transposed: 128 rows x 8 float4 (32 k)
        for (int idx = tid; idx < 1024; idx += 256) {
            int row = idx >> 3, q = idx & 7;
            int grow = r0 + row;
            float4 v = (grow < NN) ? ((const float4*)X)[(size_t)grow * 32 + kt * 8 + q]
                                   : make_float4(0.f, 0.f, 0.f, 0.f);
            xT[4 * q + 0][row] = v.x;
            xT[4 * q + 1][row] = v.y;
            xT[4 * q + 2][row] = v.z;
            xT[4 * q + 3][row] = v.w;
        }
        // load W tile: 32 k x 32 float4 (128 cols)
        for (int idx = tid; idx < 1024; idx += 256) {
            int k = idx >> 5, q = idx & 31;
            ((float4*)&Wp[k][0])[q] = ((const float4*)W)[(size_t)(kt * 32 + k) * 32 + q];
        }
        __syncthreads();

#pragma unroll 4
        for (int k = 0; k < 32; k++) {
            float4 x0 = *(const float4*)&xT[k][8 * ty];
            float4 x1 = *(const float4*)&xT[k][8 * ty + 4];
            float4 w0 = *(const float4*)&Wp[k][8 * tx];
            float4 w1 = *(const float4*)&Wp[k][8 * tx + 4];
            float2 xp[4] = {{x0.x, x0.y}, {x0.z, x0.w}, {x1.x, x1.y}, {x1.z, x1.w}};
            float wc[8] = {w0.x, w0.y, w0.z, w0.w, w1.x, w1.y, w1.z, w1.w};
#pragma unroll
            for (int c = 0; c < 8; c++) {
                float2 wb = make_float2(wc[c], wc[c]);
#pragma unroll
                for (int rp = 0; rp < 4; rp++)
                    acc[c][rp] = ffma2(xp[rp], wb, acc[c][rp]);
            }
        }
        __syncthreads();
    }

    // epilogue: scale by dinv[row], two float4 stores per row
#pragma unroll
    for (int rp = 0; rp < 4; rp++) {
#pragma unroll
        for (int hh = 0; hh < 2; hh++) {
            int row = r0 + 8 * ty + 2 * rp + hh;
            if (row < NN) {
                float di = g_dinv[row];
                float a0 = hh ? acc[0][rp].y : acc[0][rp].x;
                float a1 = hh ? acc[1][rp].y : acc[1][rp].x;
                float a2 = hh ? acc[2][rp].y : acc[2][rp].x;
                float a3 = hh ? acc[3][rp].y : acc[3][rp].x;
                float a4 = hh ? acc[4][rp].y : acc[4][rp].x;
                float a5 = hh ? acc[5][rp].y : acc[5][rp].x;
                float a6 = hh ? acc[6][rp].y : acc[6][rp].x;
                float a7 = hh ? acc[7][rp].y : acc[7][rp].x;
                *(float4*)&g_h[(size_t)row * 128 + 8 * tx] =
                    make_float4(di * a0, di * a1, di * a2, di * a3);
                *(float4*)&g_h[(size_t)row * 128 + 8 * tx + 4] =
                    make_float4(di * a4, di * a5, di * a6, di * a7);
            }
        }
    }
}

// ---------------- GEMM 128->40 (layer 3), dinv-scaled epilogue ----------------
__global__ void k_gemm3(const float* __restrict__ W) {
    constexpr int K2 = 64, OUTTOT = 40, OUTB = 40, COLT = 20, R = 16;
    __shared__ float2 Wp[K2][OUTB];
    __shared__ float2 xs[R][K2];
    const float* X = g_act;
    const int tid = threadIdx.x;
    const int nthr = COLT * 4;  // 80
    const int r0 = blockIdx.x * R;

    for (int idx = tid; idx < K2 * OUTB; idx += nthr) {
        int k2 = idx / OUTB, t = idx % OUTB;
        Wp[k2][t] = make_float2(W[(size_t)(2 * k2) * OUTTOT + t],
                                W[(size_t)(2 * k2 + 1) * OUTTOT + t]);
    }
    const float2* X2 = (const float2*)X;
    for (int idx = tid; idx < R * K2; idx += nthr) {
        int r = idx / K2, k2 = idx % K2;
        int row = r0 + r;
        xs[r][k2] = (row < NN) ? X2[(size_t)row * K2 + k2] : make_float2(0.f, 0.f);
    }
    __syncthreads();

    const int cx = tid % COLT;
    const int ry = tid / COLT;
    const int rb = ry * 4;
    float a00[4], a01[4], a10[4], a11[4];
#pragma unroll
    for (int rr = 0; rr < 4; rr++) { a00[rr] = a01[rr] = a10[rr] = a11[rr] = 0.0f; }

#pragma unroll 8
    for (int k2 = 0; k2 < K2; k2++) {
        float4 w4 = *(const float4*)&Wp[k2][2 * cx];
#pragma unroll
        for (int rr = 0; rr < 4; rr++) {
            float2 xv = xs[rb + rr][k2];
            a00[rr] = fmaf(xv.x, w4.x, a00[rr]);
            a01[rr] = fmaf(xv.y, w4.y, a01[rr]);
            a10[rr] = fmaf(xv.x, w4.z, a10[rr]);
            a11[rr] = fmaf(xv.y, w4.w, a11[rr]);
        }
    }

    const int c0 = 2 * cx;
#pragma unroll
    for (int rr = 0; rr < 4; rr++) {
        int row = r0 + rb + rr;
        if (row < NN) {
            float di = g_dinv[row];
            g_h[(size_t)row * OUTTOT + c0]     = di * (a00[rr] + a01[rr]);
            g_h[(size_t)row * OUTTOT + c0 + 1] = di * (a10[rr] + a11[rr]);
        }
    }
}

// ---------------- fused aggregation (warp per node), 128-wide + bias + relu ----------------
__global__ void k_agg128(const float* __restrict__ bias) {
    const int gid = blockIdx.x * blockDim.x + threadIdx.x;
    const int v = gid >> 5;
    if (v >= NN) return;
    const int lane = gid & 31;
    const float4* __restrict__ H = (const float4*)g_h;
    float4 acc = H[v * 32 + lane];  // self loop h'[v]
    const int n = g_cnt[v];
    const int* __restrict__ sp = g_srcs + g_rowptr[v];
    int j = 0;
    for (; j + 4 <= n; j += 4) {
        int s1 = sp[j], s2 = sp[j + 1], s3 = sp[j + 2], s4 = sp[j + 3];
        float4 t1 = H[s1 * 32 + lane];
        float4 t2 = H[s2 * 32 + lane];
        float4 t3 = H[s3 * 32 + lane];
        float4 t4 = H[s4 * 32 + lane];
        acc.x += (t1.x + t2.x) + (t3.x + t4.x);
        acc.y += (t1.y + t2.y) + (t3.y + t4.y);
        acc.z += (t1.z + t2.z) + (t3.z + t4.z);
        acc.w += (t1.w + t2.w) + (t3.w + t4.w);
    }
    for (; j < n; j++) {
        float4 t = H[sp[j] * 32 + lane];
        acc.x += t.x; acc.y += t.y; acc.z += t.z; acc.w += t.w;
    }
    const float di = g_dinv[v];
    const float4 bb = ((const float4*)bias)[lane];
    float4 o;
    o.x = fmaxf(fmaf(di, acc.x, bb.x), 0.f);
    o.y = fmaxf(fmaf(di, acc.y, bb.y), 0.f);
    o.z = fmaxf(fmaf(di, acc.z, bb.z), 0.f);
    o.w = fmaxf(fmaf(di, acc.w, bb.w), 0.f);
    ((float4*)g_act)[v * 32 + lane] = o;
}

// ---------------- fused layer-3 aggregation + bias + log_softmax ----------------
__global__ void k_agg40(const float* __restrict__ bias, float* __restrict__ out) {
    const int gid = blockIdx.x * blockDim.x + threadIdx.x;
    const int v = gid >> 5;
    if (v >= NN) return;
    const int lane = gid & 31;
    const bool act = lane < 10;  // 40 feats = 10 float4
    const float4* __restrict__ H = (const float4*)g_h;
    float4 acc = act ? H[v * 10 + lane] : make_float4(0.f, 0.f, 0.f, 0.f);
    const int n = g_cnt[v];
    const int* __restrict__ sp = g_srcs + g_rowptr[v];
    int j = 0;
    for (; j + 2 <= n; j += 2) {
        int s1 = sp[j], s2 = sp[j + 1];
        if (act) {
            float4 t1 = H[s1 * 10 + lane];
            float4 t2 = H[s2 * 10 + lane];
            acc.x += t1.x + t2.x; acc.y += t1.y + t2.y;
            acc.z += t1.z + t2.z; acc.w += t1.w + t2.w;
        }
    }
    if (j < n && act) {
        float4 t = H[sp[j] * 10 + lane];
        acc.x += t.x; acc.y += t.y; acc.z += t.z; acc.w += t.w;
    }
    const float di = g_dinv[v];
    float4 z = make_float4(0.f, 0.f, 0.f, 0.f);
    if (act) {
        const float4 bb = ((const float4*)bias)[lane];
        z.x = fmaf(di, acc.x, bb.x);
        z.y = fmaf(di, acc.y, bb.y);
        z.z = fmaf(di, acc.z, bb.z);
        z.w = fmaf(di, acc.w, bb.w);
    }
    float m = act ? fmaxf(fmaxf(z.x, z.y), fmaxf(z.z, z.w)) : -1e30f;
#pragma unroll
    for (int o = 16; o >= 1; o >>= 1) m = fmaxf(m, __shfl_xor_sync(0xffffffffu, m, o));
    float s = act ? (expf(z.x - m) + expf(z.y - m) + expf(z.z - m) + expf(z.w - m)) : 0.f;
#pragma unroll
    for (int o = 16; o >= 1; o >>= 1) s += __shfl_xor_sync(0xffffffffu, s, o);
    const float lse = m + logf(s);
    if (act) {
        ((float4*)out)[v * 10 + lane] =
            make_float4(z.x - lse, z.y - lse, z.z - lse, z.w - lse);
    }
}

// ---------------- launch ----------------
extern "C" void kernel_launch(void* const* d_in, const int* in_sizes, int n_in,
                              void* d_out, int out_size) {
    const float* x  = (const float*)d_in[0];
    const int* ei   = (const int*)d_in[1];
    const int* esrc = ei;
    const int* edst = ei + NE;
    const float* W1 = (const float*)d_in[2];
    const float* b1 = (const float*)d_in[3];
    const float* W2 = (const float*)d_in[4];
    const float* b2 = (const float*)d_in[5];
    const float* W3 = (const float*)d_in[6];
    const float* b3 = (const float*)d_in[7];
    float* out = (float*)d_out;

    const int TB = 256;
    const int nodeBlocks = (NN + TB - 1) / TB;
    const int edgeBlocks = (NE + TB - 1) / TB;
    const int warpBlocks = (NN * 32 + TB - 1) / TB;   // warp per node
    const int scanBlocks = (NN + 1023) / 1024;        // 49
    const int gemmRows = (NN + 127) / 128;            // 391
    const int gemm3Rows = (NN + 15) / 16;             // 3125

    // CSR build (launch index 3 = k_gemm2 for ncu)
    k_zcnt<<<nodeBlocks, TB>>>();                       // 0
    k_count<<<edgeBlocks, TB>>>(edst);                  // 1
    k_scan1<<<scanBlocks, 1024>>>();                    // 2 (also computes dinv)
    k_gemm2<<<gemmRows, 256>>>(x, W1);                  // 3  <- profiled
    k_scan2<<<1, 32>>>(scanBlocks);                     // 4
    k_scan3<<<nodeBlocks, TB>>>();                      // 5
    k_scatter<<<edgeBlocks, TB>>>(esrc, edst);          // 6

    // layer 1 aggregation
    k_agg128<<<warpBlocks, TB>>>(b1);                   // 7
    // layer 2
    k_gemm2<<<gemmRows, 256>>>(nullptr, W2);            // 8
    k_agg128<<<warpBlocks, TB>>>(b2);                   // 9
    // layer 3
    k_gemm3<<<gemm3Rows, 80>>>(W3);                     // 10
    k_agg40<<<warpBlocks, TB>>>(b3, out);               // 11
}

// round 10
// speedup vs baseline: 2.6542x; 1.0619x over previous
#include <cuda_runtime.h>
#include <cstdint>

#define NN 50000
#define NE 800000
#define NC 40

// ---------------- scratch (device globals, no alloc) ----------------
__device__ __align__(16) float g_h[(size_t)NN * 128];    // raw transformed features X@W
__device__ __align__(16) float g_act[(size_t)NN * 128];  // activated output (next layer input)
__device__ float g_dinv[NN];
__device__ int   g_cnt[NN];       // in-degree (dst histogram, no self loop)
__device__ int   g_fill[NN];      // scatter cursors
__device__ int   g_rowptr[NN];    // CSR row starts (exclusive scan of cnt)
__device__ int   g_srcs[NE];      // edge sources grouped by dst
__device__ int   g_bsum[64];
__device__ int   g_boff[64];

// ---------------- helpers ----------------
__device__ __forceinline__ float2 ffma2(float2 a, float2 b, float2 c) {
    unsigned long long ua = *reinterpret_cast<unsigned long long*>(&a);
    unsigned long long ub = *reinterpret_cast<unsigned long long*>(&b);
    unsigned long long uc = *reinterpret_cast<unsigned long long*>(&c);
    unsigned long long ud;
    asm("fma.rn.f32x2 %0, %1, %2, %3;" : "=l"(ud) : "l"(ua), "l"(ub), "l"(uc));
    return *reinterpret_cast<float2*>(&ud);
}

// ---------------- degree / CSR build ----------------
__global__ void k_zcnt() {
    int i = blockIdx.x * blockDim.x + threadIdx.x;
    if (i < NN) { g_cnt[i] = 0; g_fill[i] = 0; }
}

__global__ void k_count(const int* __restrict__ dst) {
    int e = blockIdx.x * blockDim.x + threadIdx.x;
    if (e < NE) atomicAdd(&g_cnt[dst[e]], 1);
}

// fused: dinv[i] = rsqrt(cnt+1)  AND  block-local exclusive scan of cnt
__global__ void k_scan1() {
    int i = blockIdx.x * 1024 + threadIdx.x;
    int v = (i < NN) ? g_cnt[i] : 0;
    if (i < NN) g_dinv[i] = rsqrtf((float)(v + 1));  // +1 self loop
    int lane = threadIdx.x & 31, wid = threadIdx.x >> 5;
    int x = v;
#pragma unroll
    for (int o = 1; o < 32; o <<= 1) {
        int y = __shfl_up_sync(0xffffffffu, x, o);
        if (lane >= o) x += y;
    }
    __shared__ int ws[32];
    if (lane == 31) ws[wid] = x;
    __syncthreads();
    if (wid == 0) {
        int s = ws[lane];
#pragma unroll
        for (int o = 1; o < 32; o <<= 1) {
            int y = __shfl_up_sync(0xffffffffu, s, o);
            if (lane >= o) s += y;
        }
        ws[lane] = s;
    }
    __syncthreads();
    int incl = x + (wid ? ws[wid - 1] : 0);
    if (i < NN) g_rowptr[i] = incl - v;
    if (threadIdx.x == 1023) g_bsum[blockIdx.x] = incl;
}

// one-warp scan over <=64 block sums
__global__ void k_scan2(int nb) {
    int lane = threadIdx.x;
    int a = (lane < nb) ? g_bsum[lane] : 0;
    int b = (lane + 32 < nb) ? g_bsum[lane + 32] : 0;
    int va = a, vb = b;
#pragma unroll
    for (int o = 1; o < 32; o <<= 1) {
        int y = __shfl_up_sync(0xffffffffu, a, o);
        if (lane >= o) a += y;
    }
    int tot = __shfl_sync(0xffffffffu, a, 31);
#pragma unroll
    for (int o = 1; o < 32; o <<= 1) {
        int y = __shfl_up_sync(0xffffffffu, b, o);
        if (lane >= o) b += y;
    }
    b += tot;
    if (lane < nb) g_boff[lane] = a - va;
    if (lane + 32 < nb) g_boff[lane + 32] = b - vb;
}

__global__ void k_scan3() {
    int i = blockIdx.x * blockDim.x + threadIdx.x;
    if (i < NN) g_rowptr[i] += g_boff[i >> 10];
}

__global__ void k_scatter(const int* __restrict__ src, const int* __restrict__ dst) {
    int e = blockIdx.x * blockDim.x + threadIdx.x;
    if (e >= NE) return;
    int d = dst[e];
    int pos = g_rowptr[d] + atomicAdd(&g_fill[d], 1);
    g_srcs[pos] = src[e];
}

// ---------------- GEMM v5: g_h = X @ W (raw), 128->128, ping-pong double buffer ----------
// 128x128 tile, 256 threads, 8x8/thread, K tiles of 32, 2 smem buffers, 1 sync/tile.
#define GTILE (32 * 132 + 32 * 128)  // floats per buffer: xT[32][132] + Wp[32][128]
__global__ __launch_bounds__(256, 2) void k_gemm2(const float* __restrict__ Xext,
                                                  const float* __restrict__ W) {
    extern __shared__ float sm[];
    const float* X = Xext ? Xext : g_act;
    const int tid = threadIdx.x;
    const int r0 = blockIdx.x * 128;
    const int tx = tid & 15;
    const int ty = tid >> 4;
    const float4* X4 = (const float4*)X;
    const float4* W4 = (const float4*)W;

    float4 xr[4], wr[4];
    // prologue: load tile 0
#pragma unroll
    for (int i = 0; i < 4; i++) {
        int idx = tid + i * 256;
        int row = idx >> 3, q = idx & 7;
        int grow = r0 + row;
        xr[i] = (grow < NN) ? X4[(size_t)grow * 32 + q] : make_float4(0.f, 0.f, 0.f, 0.f);
        int k = idx >> 5, cq = idx & 31;
        wr[i] = W4[(size_t)k * 32 + cq];
    }
    {
        float* xT = sm;
        float* Wp = sm + 32 * 132;
#pragma unroll
        for (int i = 0; i < 4; i++) {
            int idx = tid + i * 256;
            int row = idx >> 3, q = idx & 7;
            xT[(4 * q + 0) * 132 + row] = xr[i].x;
            xT[(4 * q + 1) * 132 + row] = xr[i].y;
            xT[(4 * q + 2) * 132 + row] = xr[i].z;
            xT[(4 * q + 3) * 132 + row] = xr[i].w;
            int k = idx >> 5, cq = idx & 31;
            *(float4*)&Wp[k * 128 + 4 * cq] = wr[i];
        }
    }
    __syncthreads();

    float2 acc[8][4];
#pragma unroll
    for (int c = 0; c < 8; c++)
#pragma unroll
        for (int rp = 0; rp < 4; rp++) acc[c][rp] = make_float2(0.f, 0.f);

    for (int kt = 0; kt < 4; kt++) {
        // prefetch next tile into registers (overlaps with compute below)
        if (kt < 3) {
#pragma unroll
            for (int i = 0; i < 4; i++) {
                int idx = tid + i * 256;
                int row = idx >> 3, q = idx & 7;
                int grow = r0 + row;
                xr[i] = (grow < NN) ? X4[(size_t)grow * 32 + (kt + 1) * 8 + q]
                                    : make_float4(0.f, 0.f, 0.f, 0.f);
                int k = idx >> 5, cq = idx & 31;
                wr[i] = W4[(size_t)((kt + 1) * 32 + k) * 32 + cq];
            }
        }
        const float* xT = sm + (kt & 1) * GTILE;
        const float* Wp = xT + 32 * 132;
#pragma unroll 4
        for (int k = 0; k < 32; k++) {
            float4 x0 = *(const float4*)&xT[k * 132 + 8 * ty];
            float4 x1 = *(const float4*)&xT[k * 132 + 8 * ty + 4];
            float4 w0 = *(const float4*)&Wp[k * 128 + 8 * tx];
            float4 w1 = *(const float4*)&Wp[k * 128 + 8 * tx + 4];
            float2 xp[4] = {{x0.x, x0.y}, {x0.z, x0.w}, {x1.x, x1.y}, {x1.z, x1.w}};
            float wc[8] = {w0.x, w0.y, w0.z, w0.w, w1.x, w1.y, w1.z, w1.w};
#pragma unroll
            for (int c = 0; c < 8; c++) {
                float2 wb = make_float2(wc[c], wc[c]);
#pragma unroll
                for (int rp = 0; rp < 4; rp++)
                    acc[c][rp] = ffma2(xp[rp], wb, acc[c][rp]);
            }
        }
        if (kt < 3) {
            float* xTn = sm + ((kt + 1) & 1) * GTILE;
            float* Wpn = xTn + 32 * 132;
#pragma unroll
            for (int i = 0; i < 4; i++) {
                int idx = tid + i * 256;
                int row = idx >> 3, q = idx & 7;
                xTn[(4 * q + 0) * 132 + row] = xr[i].x;
                xTn[(4 * q + 1) * 132 + row] = xr[i].y;
                xTn[(4 * q + 2) * 132 + row] = xr[i].z;
                xTn[(4 * q + 3) * 132 + row] = xr[i].w;
                int k = idx >> 5, cq = idx & 31;
                *(float4*)&Wpn[k * 128 + 4 * cq] = wr[i];
            }
        }
        __syncthreads();
    }

    // epilogue: raw X@W stores
#pragma unroll
    for (int rp = 0; rp < 4; rp++) {
#pragma unroll
        for (int hh = 0; hh < 2; hh++) {
            int row = r0 + 8 * ty + 2 * rp + hh;
            if (row < NN) {
                float a0 = hh ? acc[0][rp].y : acc[0][rp].x;
                float a1 = hh ? acc[1][rp].y : acc[1][rp].x;
                float a2 = hh ? acc[2][rp].y : acc[2][rp].x;
                float a3 = hh ? acc[3][rp].y : acc[3][rp].x;
                float a4 = hh ? acc[4][rp].y : acc[4][rp].x;
                float a5 = hh ? acc[5][rp].y : acc[5][rp].x;
                float a6 = hh ? acc[6][rp].y : acc[6][rp].x;
                float a7 = hh ? acc[7][rp].y : acc[7][rp].x;
                *(float4*)&g_h[(size_t)row * 128 + 8 * tx] = make_float4(a0, a1, a2, a3);
                *(float4*)&g_h[(size_t)row * 128 + 8 * tx + 4] = make_float4(a4, a5, a6, a7);
            }
        }
    }
}

// ---------------- GEMM 128->40 (layer 3), raw ----------------
__global__ void k_gemm3(const float* __restrict__ W) {
    constexpr int K2 = 64, OUTTOT = 40, OUTB = 40, COLT = 20, R = 16;
    __shared__ float2 Wp[K2][OUTB];
    __shared__ float2 xs[R][K2];
    const float* X = g_act;
    const int tid = threadIdx.x;
    const int nthr = COLT * 4;  // 80
    const int r0 = blockIdx.x * R;

    for (int idx = tid; idx < K2 * OUTB; idx += nthr) {
        int k2 = idx / OUTB, t = idx % OUTB;
        Wp[k2][t] = make_float2(W[(size_t)(2 * k2) * OUTTOT + t],
                                W[(size_t)(2 * k2 + 1) * OUTTOT + t]);
    }
    const float2* X2 = (const float2*)X;
    for (int idx = tid; idx < R * K2; idx += nthr) {
        int r = idx / K2, k2 = idx % K2;
        int row = r0 + r;
        xs[r][k2] = (row < NN) ? X2[(size_t)row * K2 + k2] : make_float2(0.f, 0.f);
    }
    __syncthreads();

    const int cx = tid % COLT;
    const int ry = tid / COLT;
    const int rb = ry * 4;
    float a00[4], a01[4], a10[4], a11[4];
#pragma unroll
    for (int rr = 0; rr < 4; rr++) { a00[rr] = a01[rr] = a10[rr] = a11[rr] = 0.0f; }

#pragma unroll 8
    for (int k2 = 0; k2 < K2; k2++) {
        float4 w4 = *(const float4*)&Wp[k2][2 * cx];
#pragma unroll
        for (int rr = 0; rr < 4; rr++) {
            float2 xv = xs[rb + rr][k2];
            a00[rr] = fmaf(xv.x, w4.x, a00[rr]);
            a01[rr] = fmaf(xv.y, w4.y, a01[rr]);
            a10[rr] = fmaf(xv.x, w4.z, a10[rr]);
            a11[rr] = fmaf(xv.y, w4.w, a11[rr]);
        }
    }

    const int c0 = 2 * cx;
#pragma unroll
    for (int rr = 0; rr < 4; rr++) {
        int row = r0 + rb + rr;
        if (row < NN) {
            g_h[(size_t)row * OUTTOT + c0]     = a00[rr] + a01[rr];
            g_h[(size_t)row * OUTTOT + c0 + 1] = a10[rr] + a11[rr];
        }
    }
}

// ---------------- fused aggregation (warp per node), norms applied here ----------------
__global__ void k_agg128(const float* __restrict__ bias) {
    const int gid = blockIdx.x * blockDim.x + threadIdx.x;
    const int v = gid >> 5;
    if (v >= NN) return;
    const int lane = gid & 31;
    const float4* __restrict__ H = (const float4*)g_h;
    const float di = g_dinv[v];
    float4 hv = H[v * 32 + lane];  // self loop
    float4 acc = make_float4(di * hv.x, di * hv.y, di * hv.z, di * hv.w);
    const int n = g_cnt[v];
    const int* __restrict__ sp = g_srcs + g_rowptr[v];
    int j = 0;
    for (; j + 4 <= n; j += 4) {
        int s1 = sp[j], s2 = sp[j + 1], s3 = sp[j + 2], s4 = sp[j + 3];
        float d1 = g_dinv[s1], d2 = g_dinv[s2], d3 = g_dinv[s3], d4 = g_dinv[s4];
        float4 t1 = H[s1 * 32 + lane];
        float4 t2 = H[s2 * 32 + lane];
        float4 t3 = H[s3 * 32 + lane];
        float4 t4 = H[s4 * 32 + lane];
        acc.x += d1 * t1.x + d2 * t2.x + d3 * t3.x + d4 * t4.x;
        acc.y += d1 * t1.y + d2 * t2.y + d3 * t3.y + d4 * t4.y;
        acc.z += d1 * t1.z + d2 * t2.z + d3 * t3.z + d4 * t4.z;
        acc.w += d1 * t1.w + d2 * t2.w + d3 * t3.w + d4 * t4.w;
    }
    for (; j < n; j++) {
        int s = sp[j];
        float ds = g_dinv[s];
        float4 t = H[s * 32 + lane];
        acc.x += ds * t.x; acc.y += ds * t.y; acc.z += ds * t.z; acc.w += ds * t.w;
    }
    const float4 bb = ((const float4*)bias)[lane];
    float4 o;
    o.x = fmaxf(fmaf(di, acc.x, bb.x), 0.f);
    o.y = fmaxf(fmaf(di, acc.y, bb.y), 0.f);
    o.z = fmaxf(fmaf(di, acc.z, bb.z), 0.f);
    o.w = fmaxf(fmaf(di, acc.w, bb.w), 0.f);
    ((float4*)g_act)[v * 32 + lane] = o;
}

// ---------------- fused layer-3 aggregation + bias + log_softmax ----------------
__global__ void k_agg40(const float* __restrict__ bias, float* __restrict__ out) {
    const int gid = blockIdx.x * blockDim.x + threadIdx.x;
    const int v = gid >> 5;
    if (v >= NN) return;
    const int lane = gid & 31;
    const bool act = lane < 10;  // 40 feats = 10 float4
    const float4* __restrict__ H = (const float4*)g_h;
    const float di = g_dinv[v];
    float4 acc = make_float4(0.f, 0.f, 0.f, 0.f);
    if (act) {
        float4 hv = H[v * 10 + lane];
        acc = make_float4(di * hv.x, di * hv.y, di * hv.z, di * hv.w);
    }
    const int n = g_cnt[v];
    const int* __restrict__ sp = g_srcs + g_rowptr[v];
    for (int j = 0; j < n; j++) {
        int s = sp[j];
        float ds = g_dinv[s];
        if (act) {
            float4 t = H[s * 10 + lane];
            acc.x += ds * t.x; acc.y += ds * t.y; acc.z += ds * t.z; acc.w += ds * t.w;
        }
    }
    float4 z = make_float4(0.f, 0.f, 0.f, 0.f);
    if (act) {
        const float4 bb = ((const float4*)bias)[lane];
        z.x = fmaf(di, acc.x, bb.x);
        z.y = fmaf(di, acc.y, bb.y);
        z.z = fmaf(di, acc.z, bb.z);
        z.w = fmaf(di, acc.w, bb.w);
    }
    float m = act ? fmaxf(fmaxf(z.x, z.y), fmaxf(z.z, z.w)) : -1e30f;
#pragma unroll
    for (int o = 16; o >= 1; o >>= 1) m = fmaxf(m, __shfl_xor_sync(0xffffffffu, m, o));
    float s = act ? (expf(z.x - m) + expf(z.y - m) + expf(z.z - m) + expf(z.w - m)) : 0.f;
#pragma unroll
    for (int o = 16; o >= 1; o >>= 1) s += __shfl_xor_sync(0xffffffffu, s, o);
    const float lse = m + logf(s);
    if (act) {
        ((float4*)out)[v * 10 + lane] =
            make_float4(z.x - lse, z.y - lse, z.z - lse, z.w - lse);
    }
}

// ---------------- launch ----------------
extern "C" void kernel_launch(void* const* d_in, const int* in_sizes, int n_in,
                              void* d_out, int out_size) {
    const float* x  = (const float*)d_in[0];
    const int* ei   = (const int*)d_in[1];
    const int* esrc = ei;
    const int* edst = ei + NE;
    const float* W1 = (const float*)d_in[2];
    const float* b1 = (const float*)d_in[3];
    const float* W2 = (const float*)d_in[4];
    const float* b2 = (const float*)d_in[5];
    const float* W3 = (const float*)d_in[6];
    const float* b3 = (const float*)d_in[7];
    float* out = (float*)d_out;

    const int TB = 256;
    const int nodeBlocks = (NN + TB - 1) / TB;
    const int edgeBlocks = (NE + TB - 1) / TB;
    const int warpBlocks = (NN * 32 + TB - 1) / TB;   // warp per node
    const int scanBlocks = (NN + 1023) / 1024;        // 49
    const int gemmRows = (NN + 127) / 128;            // 391
    const int gemm3Rows = (NN + 15) / 16;             // 3125
    const int gemmSmem = 2 * GTILE * 4;               // 66560 B

    static bool init = false;  // host-side resources, created once
    static cudaStream_t sB;
    static cudaEvent_t evF, evJ;
    if (!init) {
        cudaFuncSetAttribute(k_gemm2, cudaFuncAttributeMaxDynamicSharedMemorySize, gemmSmem);
        cudaStreamCreateWithFlags(&sB, cudaStreamNonBlocking);
        cudaEventCreateWithFlags(&evF, cudaEventDisableTiming);
        cudaEventCreateWithFlags(&evJ, cudaEventDisableTiming);
        init = true;
    }

    // fork: CSR build on sB, layer-1 GEMM on main stream (independent)
    cudaEventRecord(evF, 0);
    cudaStreamWaitEvent(sB, evF, 0);

    k_zcnt<<<nodeBlocks, TB, 0, sB>>>();
    k_count<<<edgeBlocks, TB, 0, sB>>>(edst);
    k_scan1<<<scanBlocks, 1024, 0, sB>>>();
    k_scan2<<<1, 32, 0, sB>>>(scanBlocks);
    k_scan3<<<nodeBlocks, TB, 0, sB>>>();
    k_scatter<<<edgeBlocks, TB, 0, sB>>>(esrc, edst);
    cudaEventRecord(evJ, sB);

    k_gemm2<<<gemmRows, 256, gemmSmem>>>(x, W1);

    // join: aggregation needs both
    cudaStreamWaitEvent(0, evJ, 0);

    k_agg128<<<warpBlocks, TB>>>(b1);
    k_gemm2<<<gemmRows, 256, gemmSmem>>>(nullptr, W2);
    k_agg128<<<warpBlocks, TB>>>(b2);
    k_gemm3<<<gemm3Rows, 80>>>(W3);
    k_agg40<<<warpBlocks, TB>>>(b3, out);
}

// round 11
// speedup vs baseline: 2.8600x; 1.0775x over previous
#include <cuda_runtime.h>
#include <cuda_fp16.h>
#include <cstdint>

#define NN 50000
#define NE 800000
#define NC 40

// ---------------- scratch (device globals, no alloc) ----------------
__device__ __align__(16) float  g_h[(size_t)NN * 64];     // fp32 h for layer 3 (40 cols)
__device__ __align__(16) __half g_hh[(size_t)NN * 128];   // fp16 packed h for layers 1/2
__device__ __align__(16) float  g_act[(size_t)NN * 128];  // activated output (next layer input)
__device__ float g_dinv[NN];
__device__ int   g_cnt[NN];       // in-degree (dst histogram, no self loop)
__device__ int   g_fill[NN];      // scatter cursors
__device__ int   g_rowptr[NN];    // CSR row starts (block-local scan; + g_boff[blk] = global)
__device__ int   g_srcs[NE];      // edge sources grouped by dst
__device__ int   g_bsum[64];
__device__ int   g_boff[64];

// ---------------- helpers ----------------
__device__ __forceinline__ float2 ffma2(float2 a, float2 b, float2 c) {
    unsigned long long ua = *reinterpret_cast<unsigned long long*>(&a);
    unsigned long long ub = *reinterpret_cast<unsigned long long*>(&b);
    unsigned long long uc = *reinterpret_cast<unsigned long long*>(&c);
    unsigned long long ud;
    asm("fma.rn.f32x2 %0, %1, %2, %3;" : "=l"(ud) : "l"(ua), "l"(ub), "l"(uc));
    return *reinterpret_cast<float2*>(&ud);
}

// ---------------- degree / CSR build ----------------
__global__ void k_zcnt() {
    int i = blockIdx.x * blockDim.x + threadIdx.x;
    if (i < NN) { g_cnt[i] = 0; g_fill[i] = 0; }
}

__global__ void k_count(const int* __restrict__ dst) {
    int e = blockIdx.x * blockDim.x + threadIdx.x;
    if (e < NE) atomicAdd(&g_cnt[dst[e]], 1);
}

// fused: dinv[i] = rsqrt(cnt+1)  AND  block-local exclusive scan of cnt
__global__ void k_scan1() {
    int i = blockIdx.x * 1024 + threadIdx.x;
    int v = (i < NN) ? g_cnt[i] : 0;
    if (i < NN) g_dinv[i] = rsqrtf((float)(v + 1));  // +1 self loop
    int lane = threadIdx.x & 31, wid = threadIdx.x >> 5;
    int x = v;
#pragma unroll
    for (int o = 1; o < 32; o <<= 1) {
        int y = __shfl_up_sync(0xffffffffu, x, o);
        if (lane >= o) x += y;
    }
    __shared__ int ws[32];
    if (lane == 31) ws[wid] = x;
    __syncthreads();
    if (wid == 0) {
        int s = ws[lane];
#pragma unroll
        for (int o = 1; o < 32; o <<= 1) {
            int y = __shfl_up_sync(0xffffffffu, s, o);
            if (lane >= o) s += y;
        }
        ws[lane] = s;
    }
    __syncthreads();
    int incl = x + (wid ? ws[wid - 1] : 0);
    if (i < NN) g_rowptr[i] = incl - v;
    if (threadIdx.x == 1023) g_bsum[blockIdx.x] = incl;
}

// one-warp scan over <=64 block sums
__global__ void k_scan2(int nb) {
    int lane = threadIdx.x;
    int a = (lane < nb) ? g_bsum[lane] : 0;
    int b = (lane + 32 < nb) ? g_bsum[lane + 32] : 0;
    int va = a, vb = b;
#pragma unroll
    for (int o = 1; o < 32; o <<= 1) {
        int y = __shfl_up_sync(0xffffffffu, a, o);
        if (lane >= o) a += y;
    }
    int tot = __shfl_sync(0xffffffffu, a, 31);
#pragma unroll
    for (int o = 1; o < 32; o <<= 1) {
        int y = __shfl_up_sync(0xffffffffu, b, o);
        if (lane >= o) b += y;
    }
    b += tot;
    if (lane < nb) g_boff[lane] = a - va;
    if (lane + 32 < nb) g_boff[lane + 32] = b - vb;
}

__global__ void k_scatter(const int* __restrict__ src, const int* __restrict__ dst) {
    int e = blockIdx.x * blockDim.x + threadIdx.x;
    if (e >= NE) return;
    int d = dst[e];
    int pos = g_rowptr[d] + g_boff[d >> 10] + atomicAdd(&g_fill[d], 1);
    g_srcs[pos] = src[e];
}

// ---------------- GEMM v6: g_hh = half(X @ W), 128->128, ping-pong double buffer ------
#define GTILE (32 * 132 + 32 * 128)  // floats per buffer: xT[32][132] + Wp[32][128]
__global__ __launch_bounds__(256, 2) void k_gemm2(const float* __restrict__ Xext,
                                                  const float* __restrict__ W) {
    extern __shared__ float sm[];
    const float* X = Xext ? Xext : g_act;
    const int tid = threadIdx.x;
    const int r0 = blockIdx.x * 128;
    const int tx = tid & 15;
    const int ty = tid >> 4;
    const float4* X4 = (const float4*)X;
    const float4* W4 = (const float4*)W;

    float4 xr[4], wr[4];
#pragma unroll
    for (int i = 0; i < 4; i++) {
        int idx = tid + i * 256;
        int row = idx >> 3, q = idx & 7;
        int grow = r0 + row;
        xr[i] = (grow < NN) ? X4[(size_t)grow * 32 + q] : make_float4(0.f, 0.f, 0.f, 0.f);
        int k = idx >> 5, cq = idx & 31;
        wr[i] = W4[(size_t)k * 32 + cq];
    }
    {
        float* xT = sm;
        float* Wp = sm + 32 * 132;
#pragma unroll
        for (int i = 0; i < 4; i++) {
            int idx = tid + i * 256;
            int row = idx >> 3, q = idx & 7;
            xT[(4 * q + 0) * 132 + row] = xr[i].x;
            xT[(4 * q + 1) * 132 + row] = xr[i].y;
            xT[(4 * q + 2) * 132 + row] = xr[i].z;
            xT[(4 * q + 3) * 132 + row] = xr[i].w;
            int k = idx >> 5, cq = idx & 31;
            *(float4*)&Wp[k * 128 + 4 * cq] = wr[i];
        }
    }
    __syncthreads();

    float2 acc[8][4];
#pragma unroll
    for (int c = 0; c < 8; c++)
#pragma unroll
        for (int rp = 0; rp < 4; rp++) acc[c][rp] = make_float2(0.f, 0.f);

    for (int kt = 0; kt < 4; kt++) {
        if (kt < 3) {
#pragma unroll
            for (int i = 0; i < 4; i++) {
                int idx = tid + i * 256;
                int row = idx >> 3, q = idx & 7;
                int grow = r0 + row;
                xr[i] = (grow < NN) ? X4[(size_t)grow * 32 + (kt + 1) * 8 + q]
                                    : make_float4(0.f, 0.f, 0.f, 0.f);
                int k = idx >> 5, cq = idx & 31;
                wr[i] = W4[(size_t)((kt + 1) * 32 + k) * 32 + cq];
            }
        }
        const float* xT = sm + (kt & 1) * GTILE;
        const float* Wp = xT + 32 * 132;
#pragma unroll 4
        for (int k = 0; k < 32; k++) {
            float4 x0 = *(const float4*)&xT[k * 132 + 8 * ty];
            float4 x1 = *(const float4*)&xT[k * 132 + 8 * ty + 4];
            float4 w0 = *(const float4*)&Wp[k * 128 + 8 * tx];
            float4 w1 = *(const float4*)&Wp[k * 128 + 8 * tx + 4];
            float2 xp[4] = {{x0.x, x0.y}, {x0.z, x0.w}, {x1.x, x1.y}, {x1.z, x1.w}};
            float wc[8] = {w0.x, w0.y, w0.z, w0.w, w1.x, w1.y, w1.z, w1.w};
#pragma unroll
            for (int c = 0; c < 8; c++) {
                float2 wb = make_float2(wc[c], wc[c]);
#pragma unroll
                for (int rp = 0; rp < 4; rp++)
                    acc[c][rp] = ffma2(xp[rp], wb, acc[c][rp]);
            }
        }
        if (kt < 3) {
            float* xTn = sm + ((kt + 1) & 1) * GTILE;
            float* Wpn = xTn + 32 * 132;
#pragma unroll
            for (int i = 0; i < 4; i++) {
                int idx = tid + i * 256;
                int row = idx >> 3, q = idx & 7;
                xTn[(4 * q + 0) * 132 + row] = xr[i].x;
                xTn[(4 * q + 1) * 132 + row] = xr[i].y;
                xTn[(4 * q + 2) * 132 + row] = xr[i].z;
                xTn[(4 * q + 3) * 132 + row] = xr[i].w;
                int k = idx >> 5, cq = idx & 31;
                *(float4*)&Wpn[k * 128 + 4 * cq] = wr[i];
            }
        }
        __syncthreads();
    }

    // epilogue: convert to fp16, one 16B store (8 halves) per row-half
#pragma unroll
    for (int rp = 0; rp < 4; rp++) {
#pragma unroll
        for (int hh = 0; hh < 2; hh++) {
            int row = r0 + 8 * ty + 2 * rp + hh;
            if (row < NN) {
                float a0 = hh ? acc[0][rp].y : acc[0][rp].x;
                float a1 = hh ? acc[1][rp].y : acc[1][rp].x;
                float a2 = hh ? acc[2][rp].y : acc[2][rp].x;
                float a3 = hh ? acc[3][rp].y : acc[3][rp].x;
                float a4 = hh ? acc[4][rp].y : acc[4][rp].x;
                float a5 = hh ? acc[5][rp].y : acc[5][rp].x;
                float a6 = hh ? acc[6][rp].y : acc[6][rp].x;
                float a7 = hh ? acc[7][rp].y : acc[7][rp].x;
                __half2 p0 = __floats2half2_rn(a0, a1);
                __half2 p1 = __floats2half2_rn(a2, a3);
                __half2 p2 = __floats2half2_rn(a4, a5);
                __half2 p3 = __floats2half2_rn(a6, a7);
                uint4 pk;
                pk.x = *reinterpret_cast<unsigned*>(&p0);
                pk.y = *reinterpret_cast<unsigned*>(&p1);
                pk.z = *reinterpret_cast<unsigned*>(&p2);
                pk.w = *reinterpret_cast<unsigned*>(&p3);
                *(uint4*)&g_hh[(size_t)row * 128 + 8 * tx] = pk;
            }
        }
    }
}

// ---------------- GEMM 128->40 (layer 3), fp32 ----------------
__global__ void k_gemm3(const float* __restrict__ W) {
    constexpr int K2 = 64, OUTTOT = 40, OUTB = 40, COLT = 20, R = 16;
    __shared__ float2 Wp[K2][OUTB];
    __shared__ float2 xs[R][K2];
    const float* X = g_act;
    const int tid = threadIdx.x;
    const int nthr = COLT * 4;  // 80
    const int r0 = blockIdx.x * R;

    for (int idx = tid; idx < K2 * OUTB; idx += nthr) {
        int k2 = idx / OUTB, t = idx % OUTB;
        Wp[k2][t] = make_float2(W[(size_t)(2 * k2) * OUTTOT + t],
                                W[(size_t)(2 * k2 + 1) * OUTTOT + t]);
    }
    const float2* X2 = (const float2*)X;
    for (int idx = tid; idx < R * K2; idx += nthr) {
        int r = idx / K2, k2 = idx % K2;
        int row = r0 + r;
        xs[r][k2] = (row < NN) ? X2[(size_t)row * K2 + k2] : make_float2(0.f, 0.f);
    }
    __syncthreads();

    const int cx = tid % COLT;
    const int ry = tid / COLT;
    const int rb = ry * 4;
    float a00[4], a01[4], a10[4], a11[4];
#pragma unroll
    for (int rr = 0; rr < 4; rr++) { a00[rr] = a01[rr] = a10[rr] = a11[rr] = 0.0f; }

#pragma unroll 8
    for (int k2 = 0; k2 < K2; k2++) {
        float4 w4 = *(const float4*)&Wp[k2][2 * cx];
#pragma unroll
        for (int rr = 0; rr < 4; rr++) {
            float2 xv = xs[rb + rr][k2];
            a00[rr] = fmaf(xv.x, w4.x, a00[rr]);
            a01[rr] = fmaf(xv.y, w4.y, a01[rr]);
            a10[rr] = fmaf(xv.x, w4.z, a10[rr]);
            a11[rr] = fmaf(xv.y, w4.w, a11[rr]);
        }
    }

    const int c0 = 2 * cx;
#pragma unroll
    for (int rr = 0; rr < 4; rr++) {
        int row = r0 + rb + rr;
        if (row < NN) {
            g_h[(size_t)row * OUTTOT + c0]     = a00[rr] + a01[rr];
            g_h[(size_t)row * OUTTOT + c0 + 1] = a10[rr] + a11[rr];
        }
    }
}

// ---------------- fused aggregation (warp per node), fp16 gather, fp32 accum ----------
__global__ void k_agg128(const float* __restrict__ bias) {
    const int gid = blockIdx.x * blockDim.x + threadIdx.x;
    const int v = gid >> 5;
    if (v >= NN) return;
    const int lane = gid & 31;
    const float di = g_dinv[v];

    // self loop
    uint2 rs = *(const uint2*)(g_hh + (size_t)v * 128 + 4 * lane);
    float2 f0 = __half22float2(*reinterpret_cast<__half2*>(&rs.x));
    float2 f1 = __half22float2(*reinterpret_cast<__half2*>(&rs.y));
    float4 acc = make_float4(di * f0.x, di * f0.y, di * f1.x, di * f1.y);

    const int n = g_cnt[v];
    const int* __restrict__ sp = g_srcs + g_rowptr[v] + g_boff[v >> 10];
    int j = 0;
    for (; j + 4 <= n; j += 4) {
        int s1 = sp[j], s2 = sp[j + 1], s3 = sp[j + 2], s4 = sp[j + 3];
        float d1 = g_dinv[s1], d2 = g_dinv[s2], d3 = g_dinv[s3], d4 = g_dinv[s4];
        uint2 r1 = *(const uint2*)(g_hh + (size_t)s1 * 128 + 4 * lane);
        uint2 r2 = *(const uint2*)(g_hh + (size_t)s2 * 128 + 4 * lane);
        uint2 r3 = *(const uint2*)(g_hh + (size_t)s3 * 128 + 4 * lane);
        uint2 r4 = *(const uint2*)(g_hh + (size_t)s4 * 128 + 4 * lane);
        float2 a1 = __half22float2(*reinterpret_cast<__half2*>(&r1.x));
        float2 b1 = __half22float2(*reinterpret_cast<__half2*>(&r1.y));
        float2 a2 = __half22float2(*reinterpret_cast<__half2*>(&r2.x));
        float2 b2 = __half22float2(*reinterpret_cast<__half2*>(&r2.y));
        float2 a3 = __half22float2(*reinterpret_cast<__half2*>(&r3.x));
        float2 b3 = __half22float2(*reinterpret_cast<__half2*>(&r3.y));
        float2 a4 = __half22float2(*reinterpret_cast<__half2*>(&r4.x));
        float2 b4 = __half22float2(*reinterpret_cast<__half2*>(&r4.y));
        acc.x += d1 * a1.x + d2 * a2.x + d3 * a3.x + d4 * a4.x;
        acc.y += d1 * a1.y + d2 * a2.y + d3 * a3.y + d4 * a4.y;
        acc.z += d1 * b1.x + d2 * b2.x + d3 * b3.x + d4 * b4.x;
        acc.w += d1 * b1.y + d2 * b2.y + d3 * b3.y + d4 * b4.y;
    }
    for (; j < n; j++) {
        int s = sp[j];
        float ds = g_dinv[s];
        uint2 r = *(const uint2*)(g_hh + (size_t)s * 128 + 4 * lane);
        float2 a = __half22float2(*reinterpret_cast<__half2*>(&r.x));
        float2 b = __half22float2(*reinterpret_cast<__half2*>(&r.y));
        acc.x += ds * a.x; acc.y += ds * a.y; acc.z += ds * b.x; acc.w += ds * b.y;
    }
    const float4 bb = ((const float4*)bias)[lane];
    float4 o;
    o.x = fmaxf(fmaf(di, acc.x, bb.x), 0.f);
    o.y = fmaxf(fmaf(di, acc.y, bb.y), 0.f);
    o.z = fmaxf(fmaf(di, acc.z, bb.z), 0.f);
    o.w = fmaxf(fmaf(di, acc.w, bb.w), 0.f);
    ((float4*)g_act)[v * 32 + lane] = o;
}

// ---------------- fused layer-3 aggregation + bias + log_softmax (fp32) ---------------
__global__ void k_agg40(const float* __restrict__ bias, float* __restrict__ out) {
    const int gid = blockIdx.x * blockDim.x + threadIdx.x;
    const int v = gid >> 5;
    if (v >= NN) return;
    const int lane = gid & 31;
    const bool act = lane < 10;  // 40 feats = 10 float4
    const float4* __restrict__ H = (const float4*)g_h;
    const float di = g_dinv[v];
    float4 acc = make_float4(0.f, 0.f, 0.f, 0.f);
    if (act) {
        float4 hv = H[v * 10 + lane];
        acc = make_float4(di * hv.x, di * hv.y, di * hv.z, di * hv.w);
    }
    const int n = g_cnt[v];
    const int* __restrict__ sp = g_srcs + g_rowptr[v] + g_boff[v >> 10];
    int j = 0;
    for (; j + 2 <= n; j += 2) {
        int s1 = sp[j], s2 = sp[j + 1];
        float d1 = g_dinv[s1], d2 = g_dinv[s2];
        if (act) {
            float4 t1 = H[s1 * 10 + lane];
            float4 t2 = H[s2 * 10 + lane];
            acc.x += d1 * t1.x + d2 * t2.x;
            acc.y += d1 * t1.y + d2 * t2.y;
            acc.z += d1 * t1.z + d2 * t2.z;
            acc.w += d1 * t1.w + d2 * t2.w;
        }
    }
    if (j < n) {
        int s = sp[j];
        float ds = g_dinv[s];
        if (act) {
            float4 t = H[s * 10 + lane];
            acc.x += ds * t.x; acc.y += ds * t.y; acc.z += ds * t.z; acc.w += ds * t.w;
        }
    }
    float4 z = make_float4(0.f, 0.f, 0.f, 0.f);
    if (act) {
        const float4 bb = ((const float4*)bias)[lane];
        z.x = fmaf(di, acc.x, bb.x);
        z.y = fmaf(di, acc.y, bb.y);
        z.z = fmaf(di, acc.z, bb.z);
        z.w = fmaf(di, acc.w, bb.w);
    }
    float m = act ? fmaxf(fmaxf(z.x, z.y), fmaxf(z.z, z.w)) : -1e30f;
#pragma unroll
    for (int o = 16; o >= 1; o >>= 1) m = fmaxf(m, __shfl_xor_sync(0xffffffffu, m, o));
    float s = act ? (expf(z.x - m) + expf(z.y - m) + expf(z.z - m) + expf(z.w - m)) : 0.f;
#pragma unroll
    for (int o = 16; o >= 1; o >>= 1) s += __shfl_xor_sync(0xffffffffu, s, o);
    const float lse = m + logf(s);
    if (act) {
        ((float4*)out)[v * 10 + lane] =
            make_float4(z.x - lse, z.y - lse, z.z - lse, z.w - lse);
    }
}

// ---------------- launch ----------------
extern "C" void kernel_launch(void* const* d_in, const int* in_sizes, int n_in,
                              void* d_out, int out_size) {
    const float* x  = (const float*)d_in[0];
    const int* ei   = (const int*)d_in[1];
    const int* esrc = ei;
    const int* edst = ei + NE;
    const float* W1 = (const float*)d_in[2];
    const float* b1 = (const float*)d_in[3];
    const float* W2 = (const float*)d_in[4];
    const float* b2 = (const float*)d_in[5];
    const float* W3 = (const float*)d_in[6];
    const float* b3 = (const float*)d_in[7];
    float* out = (float*)d_out;

    const int TB = 256;
    const int nodeBlocks = (NN + TB - 1) / TB;
    const int edgeBlocks = (NE + TB - 1) / TB;
    const int warpBlocks = (NN * 32 + TB - 1) / TB;   // warp per node
    const int scanBlocks = (NN + 1023) / 1024;        // 49
    const int gemmRows = (NN + 127) / 128;            // 391
    const int gemm3Rows = (NN + 15) / 16;             // 3125
    const int gemmSmem = 2 * GTILE * 4;               // 66560 B

    static bool init = false;  // host-side resources, created once
    static cudaStream_t sB;
    static cudaEvent_t evF, evJ;
    if (!init) {
        cudaFuncSetAttribute(k_gemm2, cudaFuncAttributeMaxDynamicSharedMemorySize, gemmSmem);
        cudaStreamCreateWithFlags(&sB, cudaStreamNonBlocking);
        cudaEventCreateWithFlags(&evF, cudaEventDisableTiming);
        cudaEventCreateWithFlags(&evJ, cudaEventDisableTiming);
        init = true;
    }

    // fork: CSR build on sB, layer-1 GEMM on main stream (independent)
    cudaEventRecord(evF, 0);
    cudaStreamWaitEvent(sB, evF, 0);

    k_zcnt<<<nodeBlocks, TB, 0, sB>>>();                // 0
    k_count<<<edgeBlocks, TB, 0, sB>>>(edst);           // 1
    k_scan1<<<scanBlocks, 1024, 0, sB>>>();             // 2
    k_gemm2<<<gemmRows, 256, gemmSmem>>>(x, W1);        // 3  <- profiled (main stream)
    k_scan2<<<1, 32, 0, sB>>>(scanBlocks);              // 4
    k_scatter<<<edgeBlocks, TB, 0, sB>>>(esrc, edst);   // 5
    cudaEventRecord(evJ, sB);

    // join: aggregation needs both
    cudaStreamWaitEvent(0, evJ, 0);

    k_agg128<<<warpBlocks, TB>>>(b1);                   // 6
    k_gemm2<<<gemmRows, 256, gemmSmem>>>(nullptr, W2);  // 7
    k_agg128<<<warpBlocks, TB>>>(b2);                   // 8
    k_gemm3<<<gemm3Rows, 80>>>(W3);                     // 9
    k_agg40<<<warpBlocks, TB>>>(b3, out);               // 10
}

// round 16
// speedup vs baseline: 3.4637x; 1.2111x over previous
#include <cuda_runtime.h>
#include <cuda_fp16.h>
#include <mma.h>
#include <cstdint>

using namespace nvcuda;

#define NN 50000
#define NE 800000
#define NC 40

// ---------------- scratch (device globals, no alloc) ----------------
__device__ __align__(16) float  g_h[(size_t)NN * 64];     // fp32 h for layer 3 (40 cols)
__device__ __align__(16) __half g_hh[(size_t)NN * 128];   // fp16 h (GEMM out, agg gather)
__device__ __align__(16) float  g_act[(size_t)NN * 128];  // fp32 activated output
__device__ __align__(16) __half g_wh[2 * 128 * 128];      // fp16 W1,W2 transposed [n][k]
__device__ float g_dinv[NN];
__device__ int   g_cnt[NN];
__device__ int   g_fill[NN];
__device__ int   g_rowptr[NN];    // block-local scan; + g_boff[blk] = global
__device__ int   g_srcs[NE];
__device__ int   g_bsum[64];
__device__ int   g_boff[64];

// ---------------- weight conversion: g_wh[n][k] = fp16(W[k][n]) ----------------
__global__ void k_wtoh(const float* __restrict__ W1, const float* __restrict__ W2) {
    int i = blockIdx.x * blockDim.x + threadIdx.x;  // over 2*16384
    if (i < 16384) {
        int k = i >> 7, n = i & 127;
        g_wh[n * 128 + k] = __float2half(W1[i]);
    } else if (i < 32768) {
        int j = i - 16384;
        int k = j >> 7, n = j & 127;
        g_wh[16384 + n * 128 + k] = __float2half(W2[j]);
    }
}

// ---------------- degree / CSR build ----------------
__global__ void k_zcnt() {
    int i = blockIdx.x * blockDim.x + threadIdx.x;
    if (i < NN) { g_cnt[i] = 0; g_fill[i] = 0; }
}

__global__ void k_count(const int* __restrict__ dst) {
    int e = blockIdx.x * blockDim.x + threadIdx.x;
    if (e < NE) atomicAdd(&g_cnt[dst[e]], 1);
}

__global__ void k_scan1() {
    int i = blockIdx.x * 1024 + threadIdx.x;
    int v = (i < NN) ? g_cnt[i] : 0;
    if (i < NN) g_dinv[i] = rsqrtf((float)(v + 1));
    int lane = threadIdx.x & 31, wid = threadIdx.x >> 5;
    int x = v;
#pragma unroll
    for (int o = 1; o < 32; o <<= 1) {
        int y = __shfl_up_sync(0xffffffffu, x, o);
        if (lane >= o) x += y;
    }
    __shared__ int ws[32];
    if (lane == 31) ws[wid] = x;
    __syncthreads();
    if (wid == 0) {
        int s = ws[lane];
#pragma unroll
        for (int o = 1; o < 32; o <<= 1) {
            int y = __shfl_up_sync(0xffffffffu, s, o);
            if (lane >= o) s += y;
        }
        ws[lane] = s;
    }
    __syncthreads();
    int incl = x + (wid ? ws[wid - 1] : 0);
    if (i < NN) g_rowptr[i] = incl - v;
    if (threadIdx.x == 1023) g_bsum[blockIdx.x] = incl;
}

__global__ void k_scan2(int nb) {
    int lane = threadIdx.x;
    int a = (lane < nb) ? g_bsum[lane] : 0;
    int b = (lane + 32 < nb) ? g_bsum[lane + 32] : 0;
    int va = a, vb = b;
#pragma unroll
    for (int o = 1; o < 32; o <<= 1) {
        int y = __shfl_up_sync(0xffffffffu, a, o);
        if (lane >= o) a += y;
    }
    int tot = __shfl_sync(0xffffffffu, a, 31);
#pragma unroll
    for (int o = 1; o < 32; o <<= 1) {
        int y = __shfl_up_sync(0xffffffffu, b, o);
        if (lane >= o) b += y;
    }
    b += tot;
    if (lane < nb) g_boff[lane] = a - va;
    if (lane + 32 < nb) g_boff[lane + 32] = b - vb;
}

__global__ void k_scatter(const int* __restrict__ src, const int* __restrict__ dst) {
    int e = blockIdx.x * blockDim.x + threadIdx.x;
    if (e >= NE) return;
    int d = dst[e];
    int pos = g_rowptr[d] + g_boff[d >> 10] + atomicAdd(&g_fill[d], 1);
    g_srcs[pos] = src[e];
}

// ---------------- wmma tensor-core GEMM: g_hh = fp16(X @ W), 128x128 tile ------------
// ALL device-global operands resolved INSIDE device code (host shadow-symbol bug fix).
// Only harness pointers cross the launch boundary.
#define XS_LD 144  // halves per smem row: 288B pitch (32B-aligned rows, ldm % 8 == 0)
template <int LAYER>  // 1: X = xext (fp32 arg), W = g_wh; 2: X = g_act, W = g_wh + 16384
__global__ __launch_bounds__(256) void k_gemmW(const float* __restrict__ xext) {
    extern __shared__ __half sh[];
    __half* sX = sh;                  // [128][XS_LD] row-major (m, k)
    __half* sW = sh + 128 * XS_LD;    // [128][XS_LD] n-major, k contiguous == col-major B
    const int tid = threadIdx.x;
    const int warp = tid >> 5, lane = tid & 31;
    const int r0 = blockIdx.x * 128;

    const float* __restrict__ Xsrc = (LAYER == 1) ? xext : g_act;   // device-side binding
    const __half* __restrict__ Wt = (LAYER == 1) ? g_wh : (g_wh + 16384);

    // fill smem: X tile (fp32 -> fp16, zero-pad OOB rows) and Wt
    for (int i = tid; i < 128 * 16; i += 256) {
        int row = i >> 4, cq = i & 15;  // cq: 16B chunk = 8 halves
        int grow = r0 + row;
        uint4 v = make_uint4(0u, 0u, 0u, 0u);
        if (grow < NN) {
            const float4* fp = (const float4*)(Xsrc + (size_t)grow * 128);
            float4 f0 = fp[2 * cq], f1 = fp[2 * cq + 1];
            __half2 h0 = __floats2half2_rn(f0.x, f0.y);
            __half2 h1 = __floats2half2_rn(f0.z, f0.w);
            __half2 h2 = __floats2half2_rn(f1.x, f1.y);
            __half2 h3 = __floats2half2_rn(f1.z, f1.w);
            v.x = *reinterpret_cast<unsigned*>(&h0);
            v.y = *reinterpret_cast<unsigned*>(&h1);
            v.z = *reinterpret_cast<unsigned*>(&h2);
            v.w = *reinterpret_cast<unsigned*>(&h3);
        }
        *(uint4*)(sX + row * XS_LD + cq * 8) = v;
    }
    for (int i = tid; i < 128 * 16; i += 256) {
        int n = i >> 4, cq = i & 15;
        *(uint4*)(sW + n * XS_LD + cq * 8) = ((const uint4*)(Wt + (size_t)n * 128))[cq];
    }
    __syncthreads();

    wmma::fragment<wmma::accumulator, 16, 16, 16, float> cf[8];
#pragma unroll
    for (int p = 0; p < 8; p++) wmma::fill_fragment(cf[p], 0.0f);

    const int mrow = warp * 16;
#pragma unroll
    for (int kk = 0; kk < 128; kk += 16) {
        wmma::fragment<wmma::matrix_a, 16, 16, 16, __half, wmma::row_major> af;
        wmma::load_matrix_sync(af, sX + mrow * XS_LD + kk, XS_LD);
#pragma unroll
        for (int p = 0; p < 8; p++) {
            wmma::fragment<wmma::matrix_b, 16, 16, 16, __half, wmma::col_major> bf;
            // col-major B: element (k, n) at sW[n * XS_LD + k]; tile origin (kk, p*16)
            wmma::load_matrix_sync(bf, sW + (p * 16) * XS_LD + kk, XS_LD);
            wmma::mma_sync(cf[p], af, bf, cf[p]);
        }
    }

    // epilogue: stage fp32 per-warp strip in (reused) smem, convert, coalesced stores
    __syncthreads();
    float* outs = (float*)sh + warp * 16 * 128;  // 8KB per warp, 64KB total (< smem alloc)
#pragma unroll
    for (int p = 0; p < 8; p++)
        wmma::store_matrix_sync(outs + p * 16, cf[p], 128, wmma::mem_row_major);
    __syncwarp();  // cross-lane smem visibility within the warp
#pragma unroll
    for (int r = 0; r < 16; r++) {
        int row = r0 + mrow + r;
        if (row < NN) {
            float4 v = *(float4*)&outs[r * 128 + lane * 4];
            __half2 p0 = __floats2half2_rn(v.x, v.y);
            __half2 p1 = __floats2half2_rn(v.z, v.w);
            uint2 pk;
            pk.x = *reinterpret_cast<unsigned*>(&p0);
            pk.y = *reinterpret_cast<unsigned*>(&p1);
            *(uint2*)&g_hh[(size_t)row * 128 + lane * 4] = pk;
        }
    }
}

// ---------------- GEMM 128->40 (layer 3), fp32 ----------------
__global__ void k_gemm3(const float* __restrict__ W) {
    constexpr int K2 = 64, OUTTOT = 40, OUTB = 40, COLT = 20, R = 16;
    __shared__ float2 Wp[K2][OUTB];
    __shared__ float2 xs[R][K2];
    const float* X = g_act;
    const int tid = threadIdx.x;
    const int nthr = COLT * 4;  // 80
    const int r0 = blockIdx.x * R;

    for (int idx = tid; idx < K2 * OUTB; idx += nthr) {
        int k2 = idx / OUTB, t = idx % OUTB;
        Wp[k2][t] = make_float2(W[(size_t)(2 * k2) * OUTTOT + t],
                                W[(size_t)(2 * k2 + 1) * OUTTOT + t]);
    }
    const float2* X2 = (const float2*)X;
    for (int idx = tid; idx < R * K2; idx += nthr) {
        int r = idx / K2, k2 = idx % K2;
        int row = r0 + r;
        xs[r][k2] = (row < NN) ? X2[(size_t)row * K2 + k2] : make_float2(0.f, 0.f);
    }
    __syncthreads();

    const int cx = tid % COLT;
    const int ry = tid / COLT;
    const int rb = ry * 4;
    float a00[4], a01[4], a10[4], a11[4];
#pragma unroll
    for (int rr = 0; rr < 4; rr++) { a00[rr] = a01[rr] = a10[rr] = a11[rr] = 0.0f; }

#pragma unroll 8
    for (int k2 = 0; k2 < K2; k2++) {
        float4 w4 = *(const float4*)&Wp[k2][2 * cx];
#pragma unroll
        for (int rr = 0; rr < 4; rr++) {
            float2 xv = xs[rb + rr][k2];
            a00[rr] = fmaf(xv.x, w4.x, a00[rr]);
            a01[rr] = fmaf(xv.y, w4.y, a01[rr]);
            a10[rr] = fmaf(xv.x, w4.z, a10[rr]);
            a11[rr] = fmaf(xv.y, w4.w, a11[rr]);
        }
    }

    const int c0 = 2 * cx;
#pragma unroll
    for (int rr = 0; rr < 4; rr++) {
        int row = r0 + rb + rr;
        if (row < NN) {
            g_h[(size_t)row * OUTTOT + c0]     = a00[rr] + a01[rr];
            g_h[(size_t)row * OUTTOT + c0 + 1] = a10[rr] + a11[rr];
        }
    }
}

// ---------------- fused aggregation (warp per node), fp16 gather, fp32 act out -------
__global__ void k_agg128(const float* __restrict__ bias) {
    const int gid = blockIdx.x * blockDim.x + threadIdx.x;
    const int v = gid >> 5;
    if (v >= NN) return;
    const int lane = gid & 31;
    const float di = g_dinv[v];

    uint2 rs = *(const uint2*)(g_hh + (size_t)v * 128 + 4 * lane);
    float2 f0 = __half22float2(*reinterpret_cast<__half2*>(&rs.x));
    float2 f1 = __half22float2(*reinterpret_cast<__half2*>(&rs.y));
    float4 acc = make_float4(di * f0.x, di * f0.y, di * f1.x, di * f1.y);

    const int n = g_cnt[v];
    const int* __restrict__ sp = g_srcs + g_rowptr[v] + g_boff[v >> 10];
    int j = 0;
    for (; j + 4 <= n; j += 4) {
        int s1 = sp[j], s2 = sp[j + 1], s3 = sp[j + 2], s4 = sp[j + 3];
        float d1 = g_dinv[s1], d2 = g_dinv[s2], d3 = g_dinv[s3], d4 = g_dinv[s4];
        uint2 r1 = *(const uint2*)(g_hh + (size_t)s1 * 128 + 4 * lane);
        uint2 r2 = *(const uint2*)(g_hh + (size_t)s2 * 128 + 4 * lane);
        uint2 r3 = *(const uint2*)(g_hh + (size_t)s3 * 128 + 4 * lane);
        uint2 r4 = *(const uint2*)(g_hh + (size_t)s4 * 128 + 4 * lane);
        float2 a1 = __half22float2(*reinterpret_cast<__half2*>(&r1.x));
        float2 b1 = __half22float2(*reinterpret_cast<__half2*>(&r1.y));
        float2 a2 = __half22float2(*reinterpret_cast<__half2*>(&r2.x));
        float2 b2 = __half22float2(*reinterpret_cast<__half2*>(&r2.y));
        float2 a3 = __half22float2(*reinterpret_cast<__half2*>(&r3.x));
        float2 b3 = __half22float2(*reinterpret_cast<__half2*>(&r3.y));
        float2 a4 = __half22float2(*reinterpret_cast<__half2*>(&r4.x));
        float2 b4 = __half22float2(*reinterpret_cast<__half2*>(&r4.y));
        acc.x += d1 * a1.x + d2 * a2.x + d3 * a3.x + d4 * a4.x;
        acc.y += d1 * a1.y + d2 * a2.y + d3 * a3.y + d4 * a4.y;
        acc.z += d1 * b1.x + d2 * b2.x + d3 * b3.x + d4 * b4.x;
        acc.w += d1 * b1.y + d2 * b2.y + d3 * b3.y + d4 * b4.y;
    }
    for (; j < n; j++) {
        int s = sp[j];
        float ds = g_dinv[s];
        uint2 r = *(const uint2*)(g_hh + (size_t)s * 128 + 4 * lane);
        float2 a = __half22float2(*reinterpret_cast<__half2*>(&r.x));
        float2 b = __half22float2(*reinterpret_cast<__half2*>(&r.y));
        acc.x += ds * a.x; acc.y += ds * a.y; acc.z += ds * b.x; acc.w += ds * b.y;
    }
    const float4 bb = ((const float4*)bias)[lane];
    float4 o;
    o.x = fmaxf(fmaf(di, acc.x, bb.x), 0.f);
    o.y = fmaxf(fmaf(di, acc.y, bb.y), 0.f);
    o.z = fmaxf(fmaf(di, acc.z, bb.z), 0.f);
    o.w = fmaxf(fmaf(di, acc.w, bb.w), 0.f);
    ((float4*)g_act)[v * 32 + lane] = o;
}

// ---------------- fused layer-3 aggregation + bias + log_softmax (fp32) ---------------
__global__ void k_agg40(const float* __restrict__ bias, float* __restrict__ out) {
    const int gid = blockIdx.x * blockDim.x + threadIdx.x;
    const int v = gid >> 5;
    if (v >= NN) return;
    const int lane = gid & 31;
    const bool act = lane < 10;
    const float4* __restrict__ H = (const float4*)g_h;
    const float di = g_dinv[v];
    float4 acc = make_float4(0.f, 0.f, 0.f, 0.f);
    if (act) {
        float4 hv = H[v * 10 + lane];
        acc = make_float4(di * hv.x, di * hv.y, di * hv.z, di * hv.w);
    }
    const int n = g_cnt[v];
    const int* __restrict__ sp = g_srcs + g_rowptr[v] + g_boff[v >> 10];
    int j = 0;
    for (; j + 2 <= n; j += 2) {
        int s1 = sp[j], s2 = sp[j + 1];
        float d1 = g_dinv[s1], d2 = g_dinv[s2];
        if (act) {
            float4 t1 = H[s1 * 10 + lane];
            float4 t2 = H[s2 * 10 + lane];
            acc.x += d1 * t1.x + d2 * t2.x;
            acc.y += d1 * t1.y + d2 * t2.y;
            acc.z += d1 * t1.z + d2 * t2.z;
            acc.w += d1 * t1.w + d2 * t2.w;
        }
    }
    if (j < n) {
        int s = sp[j];
        float ds = g_dinv[s];
        if (act) {
            float4 t = H[s * 10 + lane];
            acc.x += ds * t.x; acc.y += ds * t.y; acc.z += ds * t.z; acc.w += ds * t.w;
        }
    }
    float4 z = make_float4(0.f, 0.f, 0.f, 0.f);
    if (act) {
        const float4 bb = ((const float4*)bias)[lane];
        z.x = fmaf(di, acc.x, bb.x);
        z.y = fmaf(di, acc.y, bb.y);
        z.z = fmaf(di, acc.z, bb.z);
        z.w = fmaf(di, acc.w, bb.w);
    }
    float m = act ? fmaxf(fmaxf(z.x, z.y), fmaxf(z.z, z.w)) : -1e30f;
#pragma unroll
    for (int o = 16; o >= 1; o >>= 1) m = fmaxf(m, __shfl_xor_sync(0xffffffffu, m, o));
    float s = act ? (expf(z.x - m) + expf(z.y - m) + expf(z.z - m) + expf(z.w - m)) : 0.f;
#pragma unroll
    for (int o = 16; o >= 1; o >>= 1) s += __shfl_xor_sync(0xffffffffu, s, o);
    const float lse = m + logf(s);
    if (act) {
        ((float4*)out)[v * 10 + lane] =
            make_float4(z.x - lse, z.y - lse, z.z - lse, z.w - lse);
    }
}

// ---------------- launch ----------------
extern "C" void kernel_launch(void* const* d_in, const int* in_sizes, int n_in,
                              void* d_out, int out_size) {
    const float* x  = (const float*)d_in[0];
    const int* ei   = (const int*)d_in[1];
    const int* esrc = ei;
    const int* edst = ei + NE;
    const float* W1 = (const float*)d_in[2];
    const float* b1 = (const float*)d_in[3];
    const float* W2 = (const float*)d_in[4];
    const float* b2 = (const float*)d_in[5];
    const float* W3 = (const float*)d_in[6];
    const float* b3 = (const float*)d_in[7];
    float* out = (float*)d_out;

    const int TB = 256;
    const int nodeBlocks = (NN + TB - 1) / TB;
    const int edgeBlocks = (NE + TB - 1) / TB;
    const int warpBlocks = (NN * 32 + TB - 1) / TB;
    const int scanBlocks = (NN + 1023) / 1024;        // 49
    const int gemmRows = (NN + 127) / 128;            // 391
    const int gemm3Rows = (NN + 15) / 16;             // 3125
    const int gemmSmem = 2 * 128 * XS_LD * 2;         // 73728 B

    static bool init = false;
    static cudaStream_t sB;
    static cudaEvent_t evF, evJ;
    if (!init) {
        cudaFuncSetAttribute(k_gemmW<1>, cudaFuncAttributeMaxDynamicSharedMemorySize,
                             gemmSmem);
        cudaFuncSetAttribute(k_gemmW<2>, cudaFuncAttributeMaxDynamicSharedMemorySize,
                             gemmSmem);
        cudaStreamCreateWithFlags(&sB, cudaStreamNonBlocking);
        cudaEventCreateWithFlags(&evF, cudaEventDisableTiming);
        cudaEventCreateWithFlags(&evJ, cudaEventDisableTiming);
        init = true;
    }

    cudaEventRecord(evF, 0);
    cudaStreamWaitEvent(sB, evF, 0);

    k_wtoh<<<128, TB>>>(W1, W2);                            // 0 (main)
    k_zcnt<<<nodeBlocks, TB, 0, sB>>>();                    // 1 (sB)
    k_count<<<edgeBlocks, TB, 0, sB>>>(edst);               // 2 (sB)
    k_gemmW<1><<<gemmRows, 256, gemmSmem>>>(x);             // 3 (main) <- profiled
    k_scan1<<<scanBlocks, 1024, 0, sB>>>();                 // 4 (sB)
    k_scan2<<<1, 32, 0, sB>>>(scanBlocks);                  // 5 (sB)
    k_scatter<<<edgeBlocks, TB, 0, sB>>>(esrc, edst);       // 6 (sB)
    cudaEventRecord(evJ, sB);

    cudaStreamWaitEvent(0, evJ, 0);

    k_agg128<<<warpBlocks, TB>>>(b1);                       // 7
    k_gemmW<2><<<gemmRows, 256, gemmSmem>>>(nullptr);       // 8
    k_agg128<<<warpBlocks, TB>>>(b2);                       // 9
    k_gemm3<<<gemm3Rows, 80>>>(W3);                         // 10
    k_agg40<<<warpBlocks, TB>>>(b3, out);                   // 11
}